// round 9
// baseline (speedup 1.0000x reference)
#include <cuda_runtime.h>
#include <math.h>

#define Bq 256
#define Tt 128
#define Ff 768
#define HH 256
#define G4 1024
#define H2 512
#define G8 2048
#define NC 16
#define GXR_OFF 33554432

typedef unsigned long long ull;

__device__ __forceinline__ void fma2(ull& d, ull a, ull b) {
    asm("fma.rn.f32x2 %0,%1,%2,%0;" : "+l"(d) : "l"(a), "l"(b));
}
__device__ __forceinline__ ull pk2(float lo, float hi) {
    ull r; asm("mov.b64 %0,{%1,%2};" : "=l"(r) : "f"(lo), "f"(hi)); return r;
}
__device__ __forceinline__ float2 up2(ull v) {
    float2 r; asm("mov.b64 {%0,%1},%2;" : "=f"(r.x), "=f"(r.y) : "l"(v)); return r;
}
__device__ __forceinline__ void mma_tf32(float c[4], const unsigned a[4], const unsigned b[2]) {
    asm("mma.sync.aligned.m16n8k8.row.col.f32.tf32.tf32.f32 "
        "{%0,%1,%2,%3}, {%4,%5,%6,%7}, {%8,%9}, {%0,%1,%2,%3};"
        : "+f"(c[0]), "+f"(c[1]), "+f"(c[2]), "+f"(c[3])
        : "r"(a[0]), "r"(a[1]), "r"(a[2]), "r"(a[3]), "r"(b[0]), "r"(b[1]));
}
__device__ __forceinline__ void cpa16(unsigned dst, const float* src) {
    asm volatile("cp.async.cg.shared.global [%0], [%1], 16;" :: "r"(dst), "l"(src));
}

__device__ float g_big[67108864];
__device__ float g_hcat[Bq * Tt * H2];
__device__ float g_wpf[HH * G4];
__device__ float g_wpr[HH * G4];
__device__ float g_wps[H2 * G8];
__device__ float g_hs[2][Bq][H2];

__device__ unsigned g_cnt[16 * 32];
__device__ unsigned g_gen[16 * 32];

__device__ __forceinline__ void group_barrier(int gid, unsigned n) {
    __syncthreads();
    if (threadIdx.x == 0) {
        volatile unsigned* genp = &g_gen[gid * 32];
        unsigned gen = *genp;
        __threadfence();
        if (atomicAdd(&g_cnt[gid * 32], 1u) == n - 1u) {
            atomicExch(&g_cnt[gid * 32], 0u);
            __threadfence();
            atomicExch(&g_gen[gid * 32], gen + 1u);
        } else {
            while (*genp == gen) { }
        }
        __threadfence();
    }
    __syncthreads();
}

__global__ void pack_whh(const float* __restrict__ in, float* __restrict__ out, int H) {
    int idx = blockIdx.x * blockDim.x + threadIdx.x;
    if (idx < 4 * H * H) {
        int g = idx & 3;
        int rem = idx >> 2;
        int n = rem % H;
        int k = rem / H;
        out[idx] = in[(size_t)(g * H + n) * H + k];
    }
}

// ---------------- TF32 GEMM, cp.async double-buffered --------------------------
// smem tiles row-major [row][k], row stride 20 floats (bank-conflict-free frags).
#define GST 20
#define TSZ (128 * GST)        // floats per matrix tile
#define BUFS (2 * TSZ)         // floats per buffer (A+B)
__global__ void __launch_bounds__(256) gemm_tf32(
    const float* __restrict__ A, const float* __restrict__ W,
    const float* __restrict__ bias, float* __restrict__ C,
    int M, int N, int K)
{
    extern __shared__ float gsm[];
    unsigned smb = (unsigned)__cvta_generic_to_shared(gsm);
    int tid = threadIdx.x;
    int lane = tid & 31, wid = tid >> 5;
    int wm = wid >> 2, wn = wid & 3;
    int lq = lane >> 2, lr4 = lane & 3;
    const float* Ab = A + (size_t)blockIdx.y * 128 * K;
    const float* Wb = W + (size_t)blockIdx.x * 128 * K;
    int ldr = tid >> 1;
    int ldk = (tid & 1) * 8;

    float acc[4][4][4];
#pragma unroll
    for (int i = 0; i < 4; i++)
#pragma unroll
        for (int j = 0; j < 4; j++)
#pragma unroll
            for (int r = 0; r < 4; r++) acc[i][j][r] = 0.f;

    // prologue: tile 0 -> buf 0
    {
        unsigned da = smb + (unsigned)(0 * BUFS + ldr * GST + ldk) * 4u;
        const float* sa = Ab + (size_t)ldr * K + ldk;
        cpa16(da, sa); cpa16(da + 16, sa + 4);
        unsigned db = smb + (unsigned)(0 * BUFS + TSZ + ldr * GST + ldk) * 4u;
        const float* sb = Wb + (size_t)ldr * K + ldk;
        cpa16(db, sb); cpa16(db + 16, sb + 4);
        asm volatile("cp.async.commit_group;");
    }
    int nk = K / 16;
    for (int kt = 0; kt < nk; kt++) {
        if (kt + 1 < nk) {
            int b = (kt + 1) & 1;
            int k0 = (kt + 1) * 16;
            unsigned da = smb + (unsigned)(b * BUFS + ldr * GST + ldk) * 4u;
            const float* sa = Ab + (size_t)ldr * K + k0 + ldk;
            cpa16(da, sa); cpa16(da + 16, sa + 4);
            unsigned db = smb + (unsigned)(b * BUFS + TSZ + ldr * GST + ldk) * 4u;
            const float* sb = Wb + (size_t)ldr * K + k0 + ldk;
            cpa16(db, sb); cpa16(db + 16, sb + 4);
            asm volatile("cp.async.commit_group;");
            asm volatile("cp.async.wait_group 1;");
        } else {
            asm volatile("cp.async.wait_group 0;");
        }
        __syncthreads();
        const unsigned* Abuf = (const unsigned*)gsm + (kt & 1) * BUFS;
        const unsigned* Bbuf = Abuf + TSZ;
#pragma unroll
        for (int ks = 0; ks < 2; ks++) {
            int kb = ks * 8;
            unsigned af[4][4];
#pragma unroll
            for (int mf = 0; mf < 4; mf++) {
                int row = wm * 64 + mf * 16 + lq;
                af[mf][0] = Abuf[row * GST + kb + lr4];
                af[mf][1] = Abuf[(row + 8) * GST + kb + lr4];
                af[mf][2] = Abuf[row * GST + kb + lr4 + 4];
                af[mf][3] = Abuf[(row + 8) * GST + kb + lr4 + 4];
            }
            unsigned bf[4][2];
#pragma unroll
            for (int nf = 0; nf < 4; nf++) {
                int n = wn * 32 + nf * 8 + lq;
                bf[nf][0] = Bbuf[n * GST + kb + lr4];
                bf[nf][1] = Bbuf[n * GST + kb + lr4 + 4];
            }
#pragma unroll
            for (int mf = 0; mf < 4; mf++)
#pragma unroll
                for (int nf = 0; nf < 4; nf++)
                    mma_tf32(acc[mf][nf], af[mf], bf[nf]);
        }
        __syncthreads();
    }
#pragma unroll
    for (int nf = 0; nf < 4; nf++) {
        int col0 = blockIdx.x * 128 + wn * 32 + nf * 8 + 2 * lr4;
        float b0v = bias[col0], b1v = bias[col0 + 1];
#pragma unroll
        for (int mf = 0; mf < 4; mf++) {
            int row0 = blockIdx.y * 128 + wm * 64 + mf * 16 + lq;
            float2 o0 = make_float2(acc[mf][nf][0] + b0v, acc[mf][nf][1] + b1v);
            float2 o1 = make_float2(acc[mf][nf][2] + b0v, acc[mf][nf][3] + b1v);
            *(float2*)(C + (size_t)row0 * N + col0) = o0;
            *(float2*)(C + (size_t)(row0 + 8) * N + col0) = o1;
        }
    }
}

__device__ __forceinline__ float sigf(float x) { return 1.f / (1.f + __expf(-x)); }

// ---------------- word BiLSTM scan ---------------------------------------------
// 128 CTAs: dir(2) x bt(8) x nt(8). CTA = 32b x 32n. Group = 8 CTAs per (dir,bt).
// h_prev read from g_hcat (t=0 skips matmul). smem: W 128KB + 2 h-chunk bufs 64KB.
__global__ void __launch_bounds__(256) word_scan_kernel() {
    extern __shared__ __align__(16) float smp[];
    float* Ws = smp;                                  // [256][128]
    float4* B0 = (float4*)(smp + 32768);              // 32 rows x 128k dup (32KB)
    float4* B1 = (float4*)(smp + 32768 + 8192);
    int cta = blockIdx.x;
    int dir = cta & 1;
    int id = cta >> 1;
    int bt = id >> 3, nt = id & 7;
    int gid = dir * 8 + bt;
    const float* gxp = dir ? (g_big + GXR_OFF) : g_big;
    const float* wp  = dir ? g_wpr : g_wpf;
    int tid = threadIdx.x;
    int lane = tid & 31, wg = tid >> 5;
    int n = nt * 32 + lane;
    int b0 = bt * 32 + wg * 4;
    int sr = tid >> 3;                 // stage row 0..31
    int sq = (tid & 7) * 4;            // stage float4 base 0..28

    for (int i = tid; i < 256 * 32; i += 256) {
        int k = i >> 5, j4 = i & 31;
        ((float4*)Ws)[i] = ((const float4*)(wp + (size_t)k * G4 + nt * 128))[j4];
    }
    float c_reg[4] = {0.f, 0.f, 0.f, 0.f};
    __syncthreads();

    for (int t = 0; t < Tt; t++) {
        int tt = dir ? (Tt - 1 - t) : t;
        ull a01[4], a23[4];
#pragma unroll
        for (int u = 0; u < 4; u++) {
            const float* gp = gxp + ((size_t)(b0 + u) * Tt + tt) * G4 + n;
            a01[u] = pk2(gp[0], gp[HH]);
            a23[u] = pk2(gp[2 * HH], gp[3 * HH]);
        }
        if (t > 0) {
            int ttp = dir ? tt + 1 : tt - 1;
            const float* hs = g_hcat + ((size_t)(bt * 32 + sr) * Tt + ttp) * H2 + dir * HH;
            // stage chunk 0 (k 0..127)
#pragma unroll
            for (int j = 0; j < 4; j++) {
                int q = sq + j;
                float4 v = *(const float4*)(hs + q * 4);
                B0[sr * 64 + 2 * q]     = make_float4(v.x, v.x, v.y, v.y);
                B0[sr * 64 + 2 * q + 1] = make_float4(v.z, v.z, v.w, v.w);
            }
            __syncthreads();
            // prefetch chunk 1 (k 128..255)
            float4 pre[4];
#pragma unroll
            for (int j = 0; j < 4; j++)
                pre[j] = *(const float4*)(hs + 128 + (sq + j) * 4);
            // compute chunk 0
            {
                const ull* hrow = (const ull*)B0 + (size_t)(wg * 4) * 128;
                const float* wr = Ws + lane * 4;
#pragma unroll 8
                for (int k = 0; k < 128; k++) {
                    ulonglong2 wv = *(const ulonglong2*)(wr + k * 128);
                    ull h0 = hrow[k], h1 = hrow[128 + k], h2 = hrow[256 + k], h3 = hrow[384 + k];
                    fma2(a01[0], h0, wv.x); fma2(a23[0], h0, wv.y);
                    fma2(a01[1], h1, wv.x); fma2(a23[1], h1, wv.y);
                    fma2(a01[2], h2, wv.x); fma2(a23[2], h2, wv.y);
                    fma2(a01[3], h3, wv.x); fma2(a23[3], h3, wv.y);
                }
            }
#pragma unroll
            for (int j = 0; j < 4; j++) {
                int q = sq + j;
                float4 v = pre[j];
                B1[sr * 64 + 2 * q]     = make_float4(v.x, v.x, v.y, v.y);
                B1[sr * 64 + 2 * q + 1] = make_float4(v.z, v.z, v.w, v.w);
            }
            __syncthreads();
            // compute chunk 1
            {
                const ull* hrow = (const ull*)B1 + (size_t)(wg * 4) * 128;
                const float* wr = Ws + 128 * 128 + lane * 4;
#pragma unroll 8
                for (int k = 0; k < 128; k++) {
                    ulonglong2 wv = *(const ulonglong2*)(wr + k * 128);
                    ull h0 = hrow[k], h1 = hrow[128 + k], h2 = hrow[256 + k], h3 = hrow[384 + k];
                    fma2(a01[0], h0, wv.x); fma2(a23[0], h0, wv.y);
                    fma2(a01[1], h1, wv.x); fma2(a23[1], h1, wv.y);
                    fma2(a01[2], h2, wv.x); fma2(a23[2], h2, wv.y);
                    fma2(a01[3], h3, wv.x); fma2(a23[3], h3, wv.y);
                }
            }
        }
#pragma unroll
        for (int u = 0; u < 4; u++) {
            float2 p01 = up2(a01[u]);
            float2 p23 = up2(a23[u]);
            float ig = sigf(p01.x), fg = sigf(p01.y);
            float gg = tanhf(p23.x), og = sigf(p23.y);
            c_reg[u] = fg * c_reg[u] + ig * gg;
            float h = og * tanhf(c_reg[u]);
            g_hcat[((size_t)(b0 + u) * Tt + tt) * H2 + dir * HH + n] = h;
        }
        if (t < Tt - 1) group_barrier(gid, 8);
    }
}

// ---------------- sentence LSTM scan -------------------------------------------
// 128 CTAs: bt(4) x nt(32). CTA = 64b x 16n. Group = 32 CTAs per bt.
// smem: W 128KB + 2 h-chunk bufs 64KB (chunks of 64 k, 8 chunks).
__global__ void __launch_bounds__(256) sent_scan_kernel() {
    extern __shared__ __align__(16) float smp[];
    float* Ws = smp;                                  // [512][64]
    float4* HB[2] = { (float4*)(smp + 32768), (float4*)(smp + 32768 + 8192) };
    int cta = blockIdx.x;
    int bt = cta >> 5, nt = cta & 31;
    int tid = threadIdx.x;
    int lane = tid & 31, wg = tid >> 5;
    int nl = lane & 15, half = lane >> 4;
    int n = nt * 16 + nl;
    int b0 = bt * 64 + wg * 8 + half * 4;
    int sr = tid >> 2;                 // 0..63
    int sq = (tid & 3) * 4;            // 0..12

    for (int i = tid; i < 512 * 16; i += 256) {
        int k = i >> 4, j4 = i & 15;
        ((float4*)Ws)[i] = ((const float4*)(g_wps + (size_t)k * G8 + nt * 64))[j4];
    }
    float* hb0 = &g_hs[0][0][0];
    float* hb1 = &g_hs[1][0][0];
    float c_reg[4] = {0.f, 0.f, 0.f, 0.f};
    __syncthreads();

    for (int t = 0; t < Tt; t++) {
        const float* hp = (t & 1) ? hb1 : hb0;
        float* hn = (t & 1) ? hb0 : hb1;
        ull a01[4], a23[4];
#pragma unroll
        for (int u = 0; u < 4; u++) {
            const float* gp = g_big + ((size_t)(b0 + u) * Tt + t) * G8 + n;
            a01[u] = pk2(gp[0], gp[H2]);
            a23[u] = pk2(gp[2 * H2], gp[3 * H2]);
        }
        if (t > 0) {
            const float* hsr = hp + (size_t)(bt * 64 + sr) * H2;
            // stage chunk 0
#pragma unroll
            for (int j = 0; j < 4; j++) {
                int q = sq + j;
                float4 v = *(const float4*)(hsr + q * 4);
                HB[0][sr * 32 + 2 * q]     = make_float4(v.x, v.x, v.y, v.y);
                HB[0][sr * 32 + 2 * q + 1] = make_float4(v.z, v.z, v.w, v.w);
            }
            __syncthreads();
#pragma unroll
            for (int c = 0; c < 8; c++) {
                float4 pre[4];
                if (c < 7) {
#pragma unroll
                    for (int j = 0; j < 4; j++)
                        pre[j] = *(const float4*)(hsr + (c + 1) * 64 + (sq + j) * 4);
                }
                const ull* hrow = (const ull*)HB[c & 1] + (size_t)(wg * 8 + half * 4) * 64;
                const float* wr = Ws + c * 4096 + nl * 4;
#pragma unroll 8
                for (int k = 0; k < 64; k++) {
                    ulonglong2 wv = *(const ulonglong2*)(wr + k * 64);
                    ull h0 = hrow[k], h1 = hrow[64 + k], h2 = hrow[128 + k], h3 = hrow[192 + k];
                    fma2(a01[0], h0, wv.x); fma2(a23[0], h0, wv.y);
                    fma2(a01[1], h1, wv.x); fma2(a23[1], h1, wv.y);
                    fma2(a01[2], h2, wv.x); fma2(a23[2], h2, wv.y);
                    fma2(a01[3], h3, wv.x); fma2(a23[3], h3, wv.y);
                }
                if (c < 7) {
                    float4* nb = HB[(c + 1) & 1];
#pragma unroll
                    for (int j = 0; j < 4; j++) {
                        int q = sq + j;
                        float4 v = pre[j];
                        nb[sr * 32 + 2 * q]     = make_float4(v.x, v.x, v.y, v.y);
                        nb[sr * 32 + 2 * q + 1] = make_float4(v.z, v.z, v.w, v.w);
                    }
                }
                __syncthreads();
            }
        }
#pragma unroll
        for (int u = 0; u < 4; u++) {
            float2 p01 = up2(a01[u]);
            float2 p23 = up2(a23[u]);
            float ig = sigf(p01.x), fg = sigf(p01.y);
            float gg = tanhf(p23.x), og = sigf(p23.y);
            c_reg[u] = fg * c_reg[u] + ig * gg;
            float h = og * tanhf(c_reg[u]);
            hn[(size_t)(b0 + u) * H2 + n] = h;   // t=127 -> hb0 = hT
        }
        if (t < Tt - 1) group_barrier(bt, 32);
    }
}

// ---------------- emissions + CRF (single block) ------------------------------
__global__ void __launch_bounds__(256) crf_kernel(
    const int* __restrict__ y,
    const float* __restrict__ lin_w, const float* __restrict__ lin_b,
    const float* __restrict__ cstart, const float* __restrict__ cend,
    const float* __restrict__ ctrans, float* __restrict__ out)
{
    __shared__ float pool[NC * H2];
    __shared__ float e[Bq][NC];
    int tid = threadIdx.x;

    for (int idx = tid; idx < NC * H2 / 4; idx += 256)
        ((float4*)pool)[idx] = ((const float4*)lin_w)[idx];
    __syncthreads();
    {
        const float* hrow = &g_hs[0][tid][0];
        float acc[NC];
#pragma unroll
        for (int c = 0; c < NC; c++) acc[c] = lin_b[c];
        for (int k = 0; k < H2; k += 4) {
            float4 hv = *(const float4*)(hrow + k);
#pragma unroll
            for (int c = 0; c < NC; c++) {
                const float* wr = pool + c * H2 + k;
                acc[c] += hv.x * wr[0] + hv.y * wr[1] + hv.z * wr[2] + hv.w * wr[3];
            }
        }
#pragma unroll
        for (int c = 0; c < NC; c++) e[tid][c] = acc[c];
    }
    __syncthreads();
    if (tid < NC * NC) pool[tid] = ctrans[tid];
    __syncthreads();
    float* tr = pool;
    float* alpha = pool + 256;
    float* alpha2 = pool + 288;
    if (tid < NC) alpha[tid] = cstart[tid] + e[0][tid];
    __syncthreads();
    if (tid < 32) {
        for (int s = 1; s < Bq; s++) {
            if (tid < NC) {
                int j = tid;
                float m = -1e30f;
#pragma unroll
                for (int i = 0; i < NC; i++) m = fmaxf(m, alpha[i] + tr[i * NC + j]);
                float sum = 0.f;
#pragma unroll
                for (int i = 0; i < NC; i++) sum += expf(alpha[i] + tr[i * NC + j] - m);
                alpha2[j] = m + logf(sum) + e[s][j];
            }
            __syncwarp();
            if (tid < NC) alpha[tid] = alpha2[tid];
            __syncwarp();
        }
    }
    __syncthreads();
    if (tid == 0) {
        int yprev = y[0];
        float num = cstart[yprev] + e[0][yprev];
        for (int s = 1; s < Bq; s++) {
            int ys = y[s];
            num += tr[yprev * NC + ys] + e[s][ys];
            yprev = ys;
        }
        num += cend[yprev];
        float m = -1e30f;
        for (int i = 0; i < NC; i++) m = fmaxf(m, alpha[i] + cend[i]);
        float sum = 0.f;
        for (int i = 0; i < NC; i++) sum += expf(alpha[i] + cend[i] - m);
        out[0] = num - (m + logf(sum));
    }
}

// ---------------- launch ------------------------------------------------------
extern "C" void kernel_launch(void* const* d_in, const int* in_sizes, int n_in,
                              void* d_out, int out_size)
{
    const float* x      = (const float*)d_in[0];
    const int*   y      = (const int*)  d_in[1];
    const float* w_ih_f = (const float*)d_in[3];
    const float* w_hh_f = (const float*)d_in[4];
    const float* b_f    = (const float*)d_in[5];
    const float* w_ih_r = (const float*)d_in[6];
    const float* w_hh_r = (const float*)d_in[7];
    const float* b_r    = (const float*)d_in[8];
    const float* w_ih_s = (const float*)d_in[9];
    const float* w_hh_s = (const float*)d_in[10];
    const float* b_s    = (const float*)d_in[11];
    const float* lin_w  = (const float*)d_in[12];
    const float* lin_b  = (const float*)d_in[13];
    const float* cstart = (const float*)d_in[14];
    const float* cend   = (const float*)d_in[15];
    const float* ctrans = (const float*)d_in[16];
    float* out = (float*)d_out;

    float *gbig, *hcat, *wpf, *wpr, *wps;
    cudaGetSymbolAddress((void**)&gbig, g_big);
    cudaGetSymbolAddress((void**)&hcat, g_hcat);
    cudaGetSymbolAddress((void**)&wpf, g_wpf);
    cudaGetSymbolAddress((void**)&wpr, g_wpr);
    cudaGetSymbolAddress((void**)&wps, g_wps);

    cudaFuncSetAttribute(word_scan_kernel,
                         cudaFuncAttributeMaxDynamicSharedMemorySize, 196608);
    cudaFuncSetAttribute(sent_scan_kernel,
                         cudaFuncAttributeMaxDynamicSharedMemorySize, 196608);

    pack_whh<<<(4 * HH * HH + 255) / 256, 256>>>(w_hh_f, wpf, HH);
    pack_whh<<<(4 * HH * HH + 255) / 256, 256>>>(w_hh_r, wpr, HH);
    pack_whh<<<(4 * H2 * H2 + 255) / 256, 256>>>(w_hh_s, wps, H2);

    dim3 g1(G4 / 128, (Bq * Tt) / 128);
    gemm_tf32<<<g1, 256, BUFS * 2 * 4>>>(x, w_ih_f, b_f, gbig, Bq * Tt, G4, Ff);
    gemm_tf32<<<g1, 256, BUFS * 2 * 4>>>(x, w_ih_r, b_r, gbig + GXR_OFF, Bq * Tt, G4, Ff);

    word_scan_kernel<<<128, 256, 196608>>>();

    dim3 g2(G8 / 128, (Bq * Tt) / 128);
    gemm_tf32<<<g2, 256, BUFS * 2 * 4>>>(hcat, w_ih_s, b_s, gbig, Bq * Tt, G8, H2);

    sent_scan_kernel<<<128, 256, 196608>>>();

    crf_kernel<<<1, 256>>>(y, lin_w, lin_b, cstart, cend, ctrans, out);
}

// round 10
// speedup vs baseline: 1.0442x; 1.0442x over previous
#include <cuda_runtime.h>
#include <math.h>

#define Bq 256
#define Tt 128
#define Ff 768
#define HH 256
#define G4 1024
#define H2 512
#define G8 2048
#define NC 16
#define GXR_OFF 33554432

typedef unsigned long long ull;

__device__ __forceinline__ void fma2(ull& d, ull a, ull b) {
    asm("fma.rn.f32x2 %0,%1,%2,%0;" : "+l"(d) : "l"(a), "l"(b));
}
__device__ __forceinline__ ull pk2(float lo, float hi) {
    ull r; asm("mov.b64 %0,{%1,%2};" : "=l"(r) : "f"(lo), "f"(hi)); return r;
}
__device__ __forceinline__ float2 up2(ull v) {
    float2 r; asm("mov.b64 {%0,%1},%2;" : "=f"(r.x), "=f"(r.y) : "l"(v)); return r;
}
__device__ __forceinline__ void mma_tf32(float c[4], const unsigned a[4], const unsigned b[2]) {
    asm("mma.sync.aligned.m16n8k8.row.col.f32.tf32.tf32.f32 "
        "{%0,%1,%2,%3}, {%4,%5,%6,%7}, {%8,%9}, {%0,%1,%2,%3};"
        : "+f"(c[0]), "+f"(c[1]), "+f"(c[2]), "+f"(c[3])
        : "r"(a[0]), "r"(a[1]), "r"(a[2]), "r"(a[3]), "r"(b[0]), "r"(b[1]));
}
__device__ __forceinline__ void cpa16(unsigned dst, const float* src) {
    asm volatile("cp.async.cg.shared.global [%0], [%1], 16;" :: "r"(dst), "l"(src));
}

__device__ float g_big[67108864];
__device__ float g_hcat[Bq * Tt * H2];
__device__ float g_wpf[HH * G4];
__device__ float g_wpr[HH * G4];
__device__ float g_wps[H2 * G8];
__device__ float g_hw[2][2][Bq][HH];
__device__ float g_hs[2][Bq][H2];

__device__ unsigned g_cnt[16 * 32];
__device__ unsigned g_gen[16 * 32];

__device__ __forceinline__ void group_barrier(int gid, unsigned n) {
    __syncthreads();
    if (threadIdx.x == 0) {
        volatile unsigned* genp = &g_gen[gid * 32];
        unsigned gen = *genp;
        __threadfence();
        if (atomicAdd(&g_cnt[gid * 32], 1u) == n - 1u) {
            atomicExch(&g_cnt[gid * 32], 0u);
            __threadfence();
            atomicExch(&g_gen[gid * 32], gen + 1u);
        } else {
            while (*genp == gen) { }
        }
        __threadfence();
    }
    __syncthreads();
}

__global__ void pack_whh(const float* __restrict__ in, float* __restrict__ out, int H) {
    int idx = blockIdx.x * blockDim.x + threadIdx.x;
    if (idx < 4 * H * H) {
        int g = idx & 3;
        int rem = idx >> 2;
        int n = rem % H;
        int k = rem / H;
        out[idx] = in[(size_t)(g * H + n) * H + k];
    }
}

// ---------------- TF32 GEMM, cp.async double-buffered (round-9, kept) ---------
#define GST 20
#define TSZ (128 * GST)
#define BUFS (2 * TSZ)
__global__ void __launch_bounds__(256) gemm_tf32(
    const float* __restrict__ A, const float* __restrict__ W,
    const float* __restrict__ bias, float* __restrict__ C,
    int M, int N, int K)
{
    extern __shared__ float gsm[];
    unsigned smb = (unsigned)__cvta_generic_to_shared(gsm);
    int tid = threadIdx.x;
    int lane = tid & 31, wid = tid >> 5;
    int wm = wid >> 2, wn = wid & 3;
    int lq = lane >> 2, lr4 = lane & 3;
    const float* Ab = A + (size_t)blockIdx.y * 128 * K;
    const float* Wb = W + (size_t)blockIdx.x * 128 * K;
    int ldr = tid >> 1;
    int ldk = (tid & 1) * 8;

    float acc[4][4][4];
#pragma unroll
    for (int i = 0; i < 4; i++)
#pragma unroll
        for (int j = 0; j < 4; j++)
#pragma unroll
            for (int r = 0; r < 4; r++) acc[i][j][r] = 0.f;

    {
        unsigned da = smb + (unsigned)(ldr * GST + ldk) * 4u;
        const float* sa = Ab + (size_t)ldr * K + ldk;
        cpa16(da, sa); cpa16(da + 16, sa + 4);
        unsigned db = smb + (unsigned)(TSZ + ldr * GST + ldk) * 4u;
        const float* sb = Wb + (size_t)ldr * K + ldk;
        cpa16(db, sb); cpa16(db + 16, sb + 4);
        asm volatile("cp.async.commit_group;");
    }
    int nk = K / 16;
    for (int kt = 0; kt < nk; kt++) {
        if (kt + 1 < nk) {
            int b = (kt + 1) & 1;
            int k0 = (kt + 1) * 16;
            unsigned da = smb + (unsigned)(b * BUFS + ldr * GST + ldk) * 4u;
            const float* sa = Ab + (size_t)ldr * K + k0 + ldk;
            cpa16(da, sa); cpa16(da + 16, sa + 4);
            unsigned db = smb + (unsigned)(b * BUFS + TSZ + ldr * GST + ldk) * 4u;
            const float* sb = Wb + (size_t)ldr * K + k0 + ldk;
            cpa16(db, sb); cpa16(db + 16, sb + 4);
            asm volatile("cp.async.commit_group;");
            asm volatile("cp.async.wait_group 1;");
        } else {
            asm volatile("cp.async.wait_group 0;");
        }
        __syncthreads();
        const unsigned* Abuf = (const unsigned*)gsm + (kt & 1) * BUFS;
        const unsigned* Bbuf = Abuf + TSZ;
#pragma unroll
        for (int ks = 0; ks < 2; ks++) {
            int kb = ks * 8;
            unsigned af[4][4];
#pragma unroll
            for (int mf = 0; mf < 4; mf++) {
                int row = wm * 64 + mf * 16 + lq;
                af[mf][0] = Abuf[row * GST + kb + lr4];
                af[mf][1] = Abuf[(row + 8) * GST + kb + lr4];
                af[mf][2] = Abuf[row * GST + kb + lr4 + 4];
                af[mf][3] = Abuf[(row + 8) * GST + kb + lr4 + 4];
            }
            unsigned bf[4][2];
#pragma unroll
            for (int nf = 0; nf < 4; nf++) {
                int n = wn * 32 + nf * 8 + lq;
                bf[nf][0] = Bbuf[n * GST + kb + lr4];
                bf[nf][1] = Bbuf[n * GST + kb + lr4 + 4];
            }
#pragma unroll
            for (int mf = 0; mf < 4; mf++)
#pragma unroll
                for (int nf = 0; nf < 4; nf++)
                    mma_tf32(acc[mf][nf], af[mf], bf[nf]);
        }
        __syncthreads();
    }
#pragma unroll
    for (int nf = 0; nf < 4; nf++) {
        int col0 = blockIdx.x * 128 + wn * 32 + nf * 8 + 2 * lr4;
        float b0v = bias[col0], b1v = bias[col0 + 1];
#pragma unroll
        for (int mf = 0; mf < 4; mf++) {
            int row0 = blockIdx.y * 128 + wm * 64 + mf * 16 + lq;
            float2 o0 = make_float2(acc[mf][nf][0] + b0v, acc[mf][nf][1] + b1v);
            float2 o1 = make_float2(acc[mf][nf][2] + b0v, acc[mf][nf][3] + b1v);
            *(float2*)(C + (size_t)row0 * N + col0) = o0;
            *(float2*)(C + (size_t)(row0 + 8) * N + col0) = o1;
        }
    }
}

__device__ __forceinline__ float sigf(float x) { return 1.f / (1.f + __expf(-x)); }

// ---------------- word BiLSTM scan: 64b x 16n half-warp tiles -------------------
// 128 CTAs: dir(2) x bt(4) x nt(16). Group = 16 CTAs per (dir,bt).
// smem: W [256][64] 64KB + h dup [64][256] 128KB = 192KB.
__global__ void __launch_bounds__(256) word_scan_kernel() {
    extern __shared__ __align__(16) float smp[];
    float* Ws = smp;                                  // [256][64]
    float2* Hd = (float2*)(smp + 16384);              // [64][256] dup pairs
    int cta = blockIdx.x;
    int dir = cta & 1;
    int id = cta >> 1;
    int bt = id >> 4, nt = id & 15;
    int gid = dir * 4 + bt;
    const float* gxp = dir ? (g_big + GXR_OFF) : g_big;
    const float* wp  = dir ? g_wpr : g_wpf;
    int tid = threadIdx.x;
    int lane = tid & 31, wg = tid >> 5;
    int nl = lane & 15, half = lane >> 4;
    int n = nt * 16 + nl;
    int b0 = bt * 64 + wg * 8 + half * 4;
    int sr = tid >> 2;                 // stage row 0..63
    int sq = (tid & 3) * 16;           // stage float4 base

    for (int i = tid; i < 256 * 16; i += 256) {
        int k = i >> 4, j4 = i & 15;
        ((float4*)Ws)[i] = ((const float4*)(wp + (size_t)k * G4 + nt * 64))[j4];
    }
    float* hb0 = &g_hw[dir][0][0][0];
    float* hb1 = &g_hw[dir][1][0][0];
    float c_reg[4] = {0.f, 0.f, 0.f, 0.f};
#pragma unroll
    for (int u = 0; u < 4; u++) hb0[(size_t)(b0 + u) * HH + n] = 0.f;
    group_barrier(gid, 16);

    for (int t = 0; t < Tt; t++) {
        int tt = dir ? (Tt - 1 - t) : t;
        const float* hp = (t & 1) ? hb1 : hb0;
        float* hn = (t & 1) ? hb0 : hb1;

        // stage h (64 rows x 256 k) dup'd into smem
        {
            const float4* hsrc = (const float4*)(hp + (size_t)(bt * 64 + sr) * HH);
            float4* hdst = (float4*)(Hd + (size_t)sr * HH);
#pragma unroll
            for (int j = 0; j < 16; j++) {
                int q = sq + j;
                float4 v = hsrc[q];
                hdst[2 * q]     = make_float4(v.x, v.x, v.y, v.y);
                hdst[2 * q + 1] = make_float4(v.z, v.z, v.w, v.w);
            }
        }
        ull a01[4], a23[4];
#pragma unroll
        for (int u = 0; u < 4; u++) {
            const float* gp = gxp + ((size_t)(b0 + u) * Tt + tt) * G4 + n;
            a01[u] = pk2(gp[0], gp[HH]);
            a23[u] = pk2(gp[2 * HH], gp[3 * HH]);
        }
        __syncthreads();

        const ull* hrow = (const ull*)Hd + (size_t)(wg * 8 + half * 4) * HH;
        const float* wrow = Ws + nl * 4;
#pragma unroll 8
        for (int k = 0; k < HH; k++) {
            ulonglong2 wv = *(const ulonglong2*)(wrow + k * 64);
            ull h0 = hrow[k];
            ull h1 = hrow[HH + k];
            ull h2 = hrow[2 * HH + k];
            ull h3 = hrow[3 * HH + k];
            fma2(a01[0], h0, wv.x); fma2(a23[0], h0, wv.y);
            fma2(a01[1], h1, wv.x); fma2(a23[1], h1, wv.y);
            fma2(a01[2], h2, wv.x); fma2(a23[2], h2, wv.y);
            fma2(a01[3], h3, wv.x); fma2(a23[3], h3, wv.y);
        }
#pragma unroll
        for (int u = 0; u < 4; u++) {
            float2 p01 = up2(a01[u]);
            float2 p23 = up2(a23[u]);
            float ig = sigf(p01.x), fg = sigf(p01.y);
            float gg = tanhf(p23.x), og = sigf(p23.y);
            c_reg[u] = fg * c_reg[u] + ig * gg;
            float h = og * tanhf(c_reg[u]);
            hn[(size_t)(b0 + u) * HH + n] = h;
            g_hcat[((size_t)(b0 + u) * Tt + tt) * H2 + dir * HH + n] = h;
        }
        if (t < Tt - 1) group_barrier(gid, 16);
    }
}

// ---------------- sentence LSTM scan (round-8, kept) ----------------------------
// 128 CTAs: bt(4) x nt(32). CTA = 64b x 16n. Group = 32 CTAs per bt.
__global__ void __launch_bounds__(256) sent_scan_kernel() {
    extern __shared__ __align__(16) float smp[];
    float* Ws = smp;                                  // [512][64]
    float2* Hd = (float2*)(smp + 512 * 64);           // [64][128] dup pairs
    int cta = blockIdx.x;
    int bt = cta >> 5, nt = cta & 31;
    int tid = threadIdx.x;
    int lane = tid & 31, wg = tid >> 5;
    int nl = lane & 15, half = lane >> 4;
    int n = nt * 16 + nl;
    int b0 = bt * 64 + wg * 8 + half * 4;

    for (int i = tid; i < 512 * 16; i += 256) {
        int k = i >> 4, j4 = i & 15;
        ((float4*)Ws)[i] = ((const float4*)(g_wps + (size_t)k * G8 + nt * 64))[j4];
    }
    float* hb0 = &g_hs[0][0][0];
    float* hb1 = &g_hs[1][0][0];
    float c_reg[4] = {0.f, 0.f, 0.f, 0.f};
#pragma unroll
    for (int u = 0; u < 4; u++) hb0[(size_t)(b0 + u) * H2 + n] = 0.f;
    group_barrier(8 + bt, 32);

    for (int t = 0; t < Tt; t++) {
        const float* hp = (t & 1) ? hb1 : hb0;
        float* hn = (t & 1) ? hb0 : hb1;

        ull a01[4], a23[4];
#pragma unroll
        for (int u = 0; u < 4; u++) {
            const float* gp = g_big + ((size_t)(b0 + u) * Tt + t) * G8 + n;
            a01[u] = pk2(gp[0], gp[H2]);
            a23[u] = pk2(gp[2 * H2], gp[3 * H2]);
        }

#pragma unroll
        for (int c = 0; c < 4; c++) {
            {
                int r = tid >> 5;
                int q = tid & 31;
#pragma unroll
                for (int p = 0; p < 8; p++) {
                    int row = r + p * 8;
                    float4 v = *(const float4*)(hp + (size_t)(bt * 64 + row) * H2 + c * 128 + q * 4);
                    float4* hdst = (float4*)(Hd + (size_t)row * 128);
                    hdst[2 * q]     = make_float4(v.x, v.x, v.y, v.y);
                    hdst[2 * q + 1] = make_float4(v.z, v.z, v.w, v.w);
                }
            }
            __syncthreads();
            const ull* hrow = (const ull*)Hd + (size_t)(wg * 8 + half * 4) * 128;
            const float* wrow = Ws + (size_t)c * 128 * 64 + nl * 4;
#pragma unroll 8
            for (int k = 0; k < 128; k++) {
                ulonglong2 wv = *(const ulonglong2*)(wrow + k * 64);
                ull h0 = hrow[k];
                ull h1 = hrow[128 + k];
                ull h2 = hrow[256 + k];
                ull h3 = hrow[384 + k];
                fma2(a01[0], h0, wv.x); fma2(a23[0], h0, wv.y);
                fma2(a01[1], h1, wv.x); fma2(a23[1], h1, wv.y);
                fma2(a01[2], h2, wv.x); fma2(a23[2], h2, wv.y);
                fma2(a01[3], h3, wv.x); fma2(a23[3], h3, wv.y);
            }
            __syncthreads();
        }
#pragma unroll
        for (int u = 0; u < 4; u++) {
            float2 p01 = up2(a01[u]);
            float2 p23 = up2(a23[u]);
            float ig = sigf(p01.x), fg = sigf(p01.y);
            float gg = tanhf(p23.x), og = sigf(p23.y);
            c_reg[u] = fg * c_reg[u] + ig * gg;
            float h = og * tanhf(c_reg[u]);
            hn[(size_t)(b0 + u) * H2 + n] = h;   // t=127 -> hb0 = hT
        }
        if (t < Tt - 1) group_barrier(8 + bt, 32);
    }
}

// ---------------- emissions + CRF (single block) ------------------------------
__global__ void __launch_bounds__(256) crf_kernel(
    const int* __restrict__ y,
    const float* __restrict__ lin_w, const float* __restrict__ lin_b,
    const float* __restrict__ cstart, const float* __restrict__ cend,
    const float* __restrict__ ctrans, float* __restrict__ out)
{
    __shared__ float pool[NC * H2];
    __shared__ float e[Bq][NC];
    int tid = threadIdx.x;

    for (int idx = tid; idx < NC * H2 / 4; idx += 256)
        ((float4*)pool)[idx] = ((const float4*)lin_w)[idx];
    __syncthreads();
    {
        const float* hrow = &g_hs[0][tid][0];
        float acc[NC];
#pragma unroll
        for (int c = 0; c < NC; c++) acc[c] = lin_b[c];
        for (int k = 0; k < H2; k += 4) {
            float4 hv = *(const float4*)(hrow + k);
#pragma unroll
            for (int c = 0; c < NC; c++) {
                const float* wr = pool + c * H2 + k;
                acc[c] += hv.x * wr[0] + hv.y * wr[1] + hv.z * wr[2] + hv.w * wr[3];
            }
        }
#pragma unroll
        for (int c = 0; c < NC; c++) e[tid][c] = acc[c];
    }
    __syncthreads();
    if (tid < NC * NC) pool[tid] = ctrans[tid];
    __syncthreads();
    float* tr = pool;
    float* alpha = pool + 256;
    float* alpha2 = pool + 288;
    if (tid < NC) alpha[tid] = cstart[tid] + e[0][tid];
    __syncthreads();
    if (tid < 32) {
        for (int s = 1; s < Bq; s++) {
            if (tid < NC) {
                int j = tid;
                float m = -1e30f;
#pragma unroll
                for (int i = 0; i < NC; i++) m = fmaxf(m, alpha[i] + tr[i * NC + j]);
                float sum = 0.f;
#pragma unroll
                for (int i = 0; i < NC; i++) sum += expf(alpha[i] + tr[i * NC + j] - m);
                alpha2[j] = m + logf(sum) + e[s][j];
            }
            __syncwarp();
            if (tid < NC) alpha[tid] = alpha2[tid];
            __syncwarp();
        }
    }
    __syncthreads();
    if (tid == 0) {
        int yprev = y[0];
        float num = cstart[yprev] + e[0][yprev];
        for (int s = 1; s < Bq; s++) {
            int ys = y[s];
            num += tr[yprev * NC + ys] + e[s][ys];
            yprev = ys;
        }
        num += cend[yprev];
        float m = -1e30f;
        for (int i = 0; i < NC; i++) m = fmaxf(m, alpha[i] + cend[i]);
        float sum = 0.f;
        for (int i = 0; i < NC; i++) sum += expf(alpha[i] + cend[i] - m);
        out[0] = num - (m + logf(sum));
    }
}

// ---------------- launch ------------------------------------------------------
extern "C" void kernel_launch(void* const* d_in, const int* in_sizes, int n_in,
                              void* d_out, int out_size)
{
    const float* x      = (const float*)d_in[0];
    const int*   y      = (const int*)  d_in[1];
    const float* w_ih_f = (const float*)d_in[3];
    const float* w_hh_f = (const float*)d_in[4];
    const float* b_f    = (const float*)d_in[5];
    const float* w_ih_r = (const float*)d_in[6];
    const float* w_hh_r = (const float*)d_in[7];
    const float* b_r    = (const float*)d_in[8];
    const float* w_ih_s = (const float*)d_in[9];
    const float* w_hh_s = (const float*)d_in[10];
    const float* b_s    = (const float*)d_in[11];
    const float* lin_w  = (const float*)d_in[12];
    const float* lin_b  = (const float*)d_in[13];
    const float* cstart = (const float*)d_in[14];
    const float* cend   = (const float*)d_in[15];
    const float* ctrans = (const float*)d_in[16];
    float* out = (float*)d_out;

    float *gbig, *hcat, *wpf, *wpr, *wps;
    cudaGetSymbolAddress((void**)&gbig, g_big);
    cudaGetSymbolAddress((void**)&hcat, g_hcat);
    cudaGetSymbolAddress((void**)&wpf, g_wpf);
    cudaGetSymbolAddress((void**)&wpr, g_wpr);
    cudaGetSymbolAddress((void**)&wps, g_wps);

    cudaFuncSetAttribute(word_scan_kernel,
                         cudaFuncAttributeMaxDynamicSharedMemorySize, 196608);
    cudaFuncSetAttribute(sent_scan_kernel,
                         cudaFuncAttributeMaxDynamicSharedMemorySize, 196608);

    pack_whh<<<(4 * HH * HH + 255) / 256, 256>>>(w_hh_f, wpf, HH);
    pack_whh<<<(4 * HH * HH + 255) / 256, 256>>>(w_hh_r, wpr, HH);
    pack_whh<<<(4 * H2 * H2 + 255) / 256, 256>>>(w_hh_s, wps, H2);

    dim3 g1(G4 / 128, (Bq * Tt) / 128);
    gemm_tf32<<<g1, 256, BUFS * 2 * 4>>>(x, w_ih_f, b_f, gbig, Bq * Tt, G4, Ff);
    gemm_tf32<<<g1, 256, BUFS * 2 * 4>>>(x, w_ih_r, b_r, gbig + GXR_OFF, Bq * Tt, G4, Ff);

    word_scan_kernel<<<128, 256, 196608>>>();

    dim3 g2(G8 / 128, (Bq * Tt) / 128);
    gemm_tf32<<<g2, 256, BUFS * 2 * 4>>>(hcat, w_ih_s, b_s, gbig, Bq * Tt, G8, H2);

    sent_scan_kernel<<<128, 256, 196608>>>();

    crf_kernel<<<1, 256>>>(y, lin_w, lin_b, cstart, cend, ctrans, out);
}

// round 11
// speedup vs baseline: 1.1382x; 1.0901x over previous
#include <cuda_runtime.h>
#include <math.h>

#define Bq 256
#define Tt 128
#define Ff 768
#define HH 256
#define G4 1024
#define H2 512
#define G8 2048
#define NC 16
#define GXR_OFF 33554432

typedef unsigned long long ull;

__device__ __forceinline__ void fma2(ull& d, ull a, ull b) {
    asm("fma.rn.f32x2 %0,%1,%2,%0;" : "+l"(d) : "l"(a), "l"(b));
}
__device__ __forceinline__ ull pk2(float lo, float hi) {
    ull r; asm("mov.b64 %0,{%1,%2};" : "=l"(r) : "f"(lo), "f"(hi)); return r;
}
__device__ __forceinline__ float2 up2(ull v) {
    float2 r; asm("mov.b64 {%0,%1},%2;" : "=f"(r.x), "=f"(r.y) : "l"(v)); return r;
}
__device__ __forceinline__ void mma_tf32(float c[4], const unsigned a[4], const unsigned b[2]) {
    asm("mma.sync.aligned.m16n8k8.row.col.f32.tf32.tf32.f32 "
        "{%0,%1,%2,%3}, {%4,%5,%6,%7}, {%8,%9}, {%0,%1,%2,%3};"
        : "+f"(c[0]), "+f"(c[1]), "+f"(c[2]), "+f"(c[3])
        : "r"(a[0]), "r"(a[1]), "r"(a[2]), "r"(a[3]), "r"(b[0]), "r"(b[1]));
}
__device__ __forceinline__ void cpa16(unsigned dst, const float* src) {
    asm volatile("cp.async.cg.shared.global [%0], [%1], 16;" :: "r"(dst), "l"(src));
}

__device__ float g_big[67108864];
__device__ float g_hcat[Bq * Tt * H2];
__device__ float g_wpf[HH * G4];
__device__ float g_wpr[HH * G4];
__device__ float g_wps[H2 * G8];
__device__ float g_hw[2][2][Bq][HH];
__device__ float g_hs[2][Bq][H2];

__device__ unsigned g_cnt[16 * 32];
__device__ unsigned g_gen[16 * 32];

__device__ __forceinline__ void group_barrier(int gid, unsigned n) {
    __syncthreads();
    if (threadIdx.x == 0) {
        volatile unsigned* genp = &g_gen[gid * 32];
        unsigned gen = *genp;
        __threadfence();
        if (atomicAdd(&g_cnt[gid * 32], 1u) == n - 1u) {
            atomicExch(&g_cnt[gid * 32], 0u);
            __threadfence();
            atomicExch(&g_gen[gid * 32], gen + 1u);
        } else {
            while (*genp == gen) { }
        }
        __threadfence();
    }
    __syncthreads();
}

__global__ void pack_whh(const float* __restrict__ in, float* __restrict__ out, int H) {
    int idx = blockIdx.x * blockDim.x + threadIdx.x;
    if (idx < 4 * H * H) {
        int g = idx & 3;
        int rem = idx >> 2;
        int n = rem % H;
        int k = rem / H;
        out[idx] = in[(size_t)(g * H + n) * H + k];
    }
}

// ---------------- TF32 GEMM, cp.async double-buffered (round-9, kept) ---------
#define GST 20
#define TSZ (128 * GST)
#define BUFS (2 * TSZ)
__global__ void __launch_bounds__(256) gemm_tf32(
    const float* __restrict__ A, const float* __restrict__ W,
    const float* __restrict__ bias, float* __restrict__ C,
    int M, int N, int K)
{
    extern __shared__ float gsm[];
    unsigned smb = (unsigned)__cvta_generic_to_shared(gsm);
    int tid = threadIdx.x;
    int lane = tid & 31, wid = tid >> 5;
    int wm = wid >> 2, wn = wid & 3;
    int lq = lane >> 2, lr4 = lane & 3;
    const float* Ab = A + (size_t)blockIdx.y * 128 * K;
    const float* Wb = W + (size_t)blockIdx.x * 128 * K;
    int ldr = tid >> 1;
    int ldk = (tid & 1) * 8;

    float acc[4][4][4];
#pragma unroll
    for (int i = 0; i < 4; i++)
#pragma unroll
        for (int j = 0; j < 4; j++)
#pragma unroll
            for (int r = 0; r < 4; r++) acc[i][j][r] = 0.f;

    {
        unsigned da = smb + (unsigned)(ldr * GST + ldk) * 4u;
        const float* sa = Ab + (size_t)ldr * K + ldk;
        cpa16(da, sa); cpa16(da + 16, sa + 4);
        unsigned db = smb + (unsigned)(TSZ + ldr * GST + ldk) * 4u;
        const float* sb = Wb + (size_t)ldr * K + ldk;
        cpa16(db, sb); cpa16(db + 16, sb + 4);
        asm volatile("cp.async.commit_group;");
    }
    int nk = K / 16;
    for (int kt = 0; kt < nk; kt++) {
        if (kt + 1 < nk) {
            int b = (kt + 1) & 1;
            int k0 = (kt + 1) * 16;
            unsigned da = smb + (unsigned)(b * BUFS + ldr * GST + ldk) * 4u;
            const float* sa = Ab + (size_t)ldr * K + k0 + ldk;
            cpa16(da, sa); cpa16(da + 16, sa + 4);
            unsigned db = smb + (unsigned)(b * BUFS + TSZ + ldr * GST + ldk) * 4u;
            const float* sb = Wb + (size_t)ldr * K + k0 + ldk;
            cpa16(db, sb); cpa16(db + 16, sb + 4);
            asm volatile("cp.async.commit_group;");
            asm volatile("cp.async.wait_group 1;");
        } else {
            asm volatile("cp.async.wait_group 0;");
        }
        __syncthreads();
        const unsigned* Abuf = (const unsigned*)gsm + (kt & 1) * BUFS;
        const unsigned* Bbuf = Abuf + TSZ;
#pragma unroll
        for (int ks = 0; ks < 2; ks++) {
            int kb = ks * 8;
            unsigned af[4][4];
#pragma unroll
            for (int mf = 0; mf < 4; mf++) {
                int row = wm * 64 + mf * 16 + lq;
                af[mf][0] = Abuf[row * GST + kb + lr4];
                af[mf][1] = Abuf[(row + 8) * GST + kb + lr4];
                af[mf][2] = Abuf[row * GST + kb + lr4 + 4];
                af[mf][3] = Abuf[(row + 8) * GST + kb + lr4 + 4];
            }
            unsigned bf[4][2];
#pragma unroll
            for (int nf = 0; nf < 4; nf++) {
                int n = wn * 32 + nf * 8 + lq;
                bf[nf][0] = Bbuf[n * GST + kb + lr4];
                bf[nf][1] = Bbuf[n * GST + kb + lr4 + 4];
            }
#pragma unroll
            for (int mf = 0; mf < 4; mf++)
#pragma unroll
                for (int nf = 0; nf < 4; nf++)
                    mma_tf32(acc[mf][nf], af[mf], bf[nf]);
        }
        __syncthreads();
    }
#pragma unroll
    for (int nf = 0; nf < 4; nf++) {
        int col0 = blockIdx.x * 128 + wn * 32 + nf * 8 + 2 * lr4;
        float b0v = bias[col0], b1v = bias[col0 + 1];
#pragma unroll
        for (int mf = 0; mf < 4; mf++) {
            int row0 = blockIdx.y * 128 + wm * 64 + mf * 16 + lq;
            float2 o0 = make_float2(acc[mf][nf][0] + b0v, acc[mf][nf][1] + b1v);
            float2 o1 = make_float2(acc[mf][nf][2] + b0v, acc[mf][nf][3] + b1v);
            *(float2*)(C + (size_t)row0 * N + col0) = o0;
            *(float2*)(C + (size_t)(row0 + 8) * N + col0) = o1;
        }
    }
}

__device__ __forceinline__ float sigf(float x) { return 1.f / (1.f + __expf(-x)); }

// ---------------- word BiLSTM scan (round-8 structure) --------------------------
// 128 CTAs: dir(2) x bt(8) x nt(8). CTA = 32b x 32n. Group = 8 CTAs per (dir,bt).
// smem: W [256][128] 128KB + h dup [32][256] 64KB = 192KB.
__global__ void __launch_bounds__(256) word_scan_kernel() {
    extern __shared__ __align__(16) float smp[];
    float* Ws = smp;                                  // [256][128]
    float2* Hd = (float2*)(smp + 256 * 128);          // [32][256] dup pairs
    int cta = blockIdx.x;
    int dir = cta & 1;
    int id = cta >> 1;
    int bt = id >> 3, nt = id & 7;
    int gid = dir * 8 + bt;
    const float* gxp = dir ? (g_big + GXR_OFF) : g_big;
    const float* wp  = dir ? g_wpr : g_wpf;
    int tid = threadIdx.x;
    int lane = tid & 31, wg = tid >> 5;
    int n = nt * 32 + lane;
    int b0 = bt * 32 + wg * 4;

    for (int i = tid; i < 256 * 32; i += 256) {
        int k = i >> 5, j4 = i & 31;
        ((float4*)Ws)[i] = ((const float4*)(wp + (size_t)k * G4 + nt * 128))[j4];
    }
    float* hb0 = &g_hw[dir][0][0][0];
    float* hb1 = &g_hw[dir][1][0][0];
    float c_reg[4] = {0.f, 0.f, 0.f, 0.f};
#pragma unroll
    for (int u = 0; u < 4; u++) hb0[(size_t)(b0 + u) * HH + n] = 0.f;
    group_barrier(gid, 8);

    for (int t = 0; t < Tt; t++) {
        int tt = dir ? (Tt - 1 - t) : t;
        const float* hp = (t & 1) ? hb1 : hb0;
        float* hn = (t & 1) ? hb0 : hb1;

        // stage h (32 rows x 256 k) dup'd into smem
        {
            const float4* hsrc = (const float4*)(hp + (size_t)(bt * 32) * HH);
            float4* hdst = (float4*)Hd;
            for (int idx = tid; idx < 32 * HH / 4; idx += 256) {
                float4 v = hsrc[idx];
                hdst[2 * idx]     = make_float4(v.x, v.x, v.y, v.y);
                hdst[2 * idx + 1] = make_float4(v.z, v.z, v.w, v.w);
            }
        }
        ull a01[4], a23[4];
#pragma unroll
        for (int u = 0; u < 4; u++) {
            const float* gp = gxp + ((size_t)(b0 + u) * Tt + tt) * G4 + n;
            a01[u] = pk2(gp[0], gp[HH]);
            a23[u] = pk2(gp[2 * HH], gp[3 * HH]);
        }
        __syncthreads();

        const ull* hrow = (const ull*)Hd + (size_t)(wg * 4) * HH;
        const float* wrow = Ws + lane * 4;
#pragma unroll 8
        for (int k = 0; k < HH; k++) {
            ulonglong2 wv = *(const ulonglong2*)(wrow + k * 128);
            ull h0 = hrow[k];
            ull h1 = hrow[HH + k];
            ull h2 = hrow[2 * HH + k];
            ull h3 = hrow[3 * HH + k];
            fma2(a01[0], h0, wv.x); fma2(a23[0], h0, wv.y);
            fma2(a01[1], h1, wv.x); fma2(a23[1], h1, wv.y);
            fma2(a01[2], h2, wv.x); fma2(a23[2], h2, wv.y);
            fma2(a01[3], h3, wv.x); fma2(a23[3], h3, wv.y);
        }
#pragma unroll
        for (int u = 0; u < 4; u++) {
            float2 p01 = up2(a01[u]);
            float2 p23 = up2(a23[u]);
            float ig = sigf(p01.x), fg = sigf(p01.y);
            float gg = tanhf(p23.x), og = sigf(p23.y);
            c_reg[u] = fg * c_reg[u] + ig * gg;
            float h = og * tanhf(c_reg[u]);
            hn[(size_t)(b0 + u) * HH + n] = h;
            g_hcat[((size_t)(b0 + u) * Tt + tt) * H2 + dir * HH + n] = h;
        }
        if (t < Tt - 1) group_barrier(gid, 8);
    }
}

// ---------------- sentence LSTM scan (round-8 structure) ------------------------
// 128 CTAs: bt(4) x nt(32). CTA = 64b x 16n. Group = 32 CTAs per bt.
__global__ void __launch_bounds__(256) sent_scan_kernel() {
    extern __shared__ __align__(16) float smp[];
    float* Ws = smp;                                  // [512][64]
    float2* Hd = (float2*)(smp + 512 * 64);           // [64][128] dup pairs
    int cta = blockIdx.x;
    int bt = cta >> 5, nt = cta & 31;
    int tid = threadIdx.x;
    int lane = tid & 31, wg = tid >> 5;
    int nl = lane & 15, half = lane >> 4;
    int n = nt * 16 + nl;
    int b0 = bt * 64 + wg * 8 + half * 4;

    for (int i = tid; i < 512 * 16; i += 256) {
        int k = i >> 4, j4 = i & 15;
        ((float4*)Ws)[i] = ((const float4*)(g_wps + (size_t)k * G8 + nt * 64))[j4];
    }
    float* hb0 = &g_hs[0][0][0];
    float* hb1 = &g_hs[1][0][0];
    float c_reg[4] = {0.f, 0.f, 0.f, 0.f};
#pragma unroll
    for (int u = 0; u < 4; u++) hb0[(size_t)(b0 + u) * H2 + n] = 0.f;
    group_barrier(8 + bt, 32);

    for (int t = 0; t < Tt; t++) {
        const float* hp = (t & 1) ? hb1 : hb0;
        float* hn = (t & 1) ? hb0 : hb1;

        ull a01[4], a23[4];
#pragma unroll
        for (int u = 0; u < 4; u++) {
            const float* gp = g_big + ((size_t)(b0 + u) * Tt + t) * G8 + n;
            a01[u] = pk2(gp[0], gp[H2]);
            a23[u] = pk2(gp[2 * H2], gp[3 * H2]);
        }

#pragma unroll
        for (int c = 0; c < 4; c++) {
            {
                int r = tid >> 5;
                int q = tid & 31;
#pragma unroll
                for (int p = 0; p < 8; p++) {
                    int row = r + p * 8;
                    float4 v = *(const float4*)(hp + (size_t)(bt * 64 + row) * H2 + c * 128 + q * 4);
                    float4* hdst = (float4*)(Hd + (size_t)row * 128);
                    hdst[2 * q]     = make_float4(v.x, v.x, v.y, v.y);
                    hdst[2 * q + 1] = make_float4(v.z, v.z, v.w, v.w);
                }
            }
            __syncthreads();
            const ull* hrow = (const ull*)Hd + (size_t)(wg * 8 + half * 4) * 128;
            const float* wrow = Ws + (size_t)c * 128 * 64 + nl * 4;
#pragma unroll 8
            for (int k = 0; k < 128; k++) {
                ulonglong2 wv = *(const ulonglong2*)(wrow + k * 64);
                ull h0 = hrow[k];
                ull h1 = hrow[128 + k];
                ull h2 = hrow[256 + k];
                ull h3 = hrow[384 + k];
                fma2(a01[0], h0, wv.x); fma2(a23[0], h0, wv.y);
                fma2(a01[1], h1, wv.x); fma2(a23[1], h1, wv.y);
                fma2(a01[2], h2, wv.x); fma2(a23[2], h2, wv.y);
                fma2(a01[3], h3, wv.x); fma2(a23[3], h3, wv.y);
            }
            __syncthreads();
        }
#pragma unroll
        for (int u = 0; u < 4; u++) {
            float2 p01 = up2(a01[u]);
            float2 p23 = up2(a23[u]);
            float ig = sigf(p01.x), fg = sigf(p01.y);
            float gg = tanhf(p23.x), og = sigf(p23.y);
            c_reg[u] = fg * c_reg[u] + ig * gg;
            float h = og * tanhf(c_reg[u]);
            hn[(size_t)(b0 + u) * H2 + n] = h;   // t=127 -> hb0 = hT
        }
        if (t < Tt - 1) group_barrier(8 + bt, 32);
    }
}

// ---------------- emissions + CRF (single block) ------------------------------
__global__ void __launch_bounds__(256) crf_kernel(
    const int* __restrict__ y,
    const float* __restrict__ lin_w, const float* __restrict__ lin_b,
    const float* __restrict__ cstart, const float* __restrict__ cend,
    const float* __restrict__ ctrans, float* __restrict__ out)
{
    __shared__ float pool[NC * H2];
    __shared__ float e[Bq][NC];
    int tid = threadIdx.x;

    for (int idx = tid; idx < NC * H2 / 4; idx += 256)
        ((float4*)pool)[idx] = ((const float4*)lin_w)[idx];
    __syncthreads();
    {
        const float* hrow = &g_hs[0][tid][0];
        float acc[NC];
#pragma unroll
        for (int c = 0; c < NC; c++) acc[c] = lin_b[c];
        for (int k = 0; k < H2; k += 4) {
            float4 hv = *(const float4*)(hrow + k);
#pragma unroll
            for (int c = 0; c < NC; c++) {
                const float* wr = pool + c * H2 + k;
                acc[c] += hv.x * wr[0] + hv.y * wr[1] + hv.z * wr[2] + hv.w * wr[3];
            }
        }
#pragma unroll
        for (int c = 0; c < NC; c++) e[tid][c] = acc[c];
    }
    __syncthreads();
    if (tid < NC * NC) pool[tid] = ctrans[tid];
    __syncthreads();
    float* tr = pool;
    float* alpha = pool + 256;
    float* alpha2 = pool + 288;
    if (tid < NC) alpha[tid] = cstart[tid] + e[0][tid];
    __syncthreads();
    if (tid < 32) {
        for (int s = 1; s < Bq; s++) {
            if (tid < NC) {
                int j = tid;
                float m = -1e30f;
#pragma unroll
                for (int i = 0; i < NC; i++) m = fmaxf(m, alpha[i] + tr[i * NC + j]);
                float sum = 0.f;
#pragma unroll
                for (int i = 0; i < NC; i++) sum += expf(alpha[i] + tr[i * NC + j] - m);
                alpha2[j] = m + logf(sum) + e[s][j];
            }
            __syncwarp();
            if (tid < NC) alpha[tid] = alpha2[tid];
            __syncwarp();
        }
    }
    __syncthreads();
    if (tid == 0) {
        int yprev = y[0];
        float num = cstart[yprev] + e[0][yprev];
        for (int s = 1; s < Bq; s++) {
            int ys = y[s];
            num += tr[yprev * NC + ys] + e[s][ys];
            yprev = ys;
        }
        num += cend[yprev];
        float m = -1e30f;
        for (int i = 0; i < NC; i++) m = fmaxf(m, alpha[i] + cend[i]);
        float sum = 0.f;
        for (int i = 0; i < NC; i++) sum += expf(alpha[i] + cend[i] - m);
        out[0] = num - (m + logf(sum));
    }
}

// ---------------- launch ------------------------------------------------------
extern "C" void kernel_launch(void* const* d_in, const int* in_sizes, int n_in,
                              void* d_out, int out_size)
{
    const float* x      = (const float*)d_in[0];
    const int*   y      = (const int*)  d_in[1];
    const float* w_ih_f = (const float*)d_in[3];
    const float* w_hh_f = (const float*)d_in[4];
    const float* b_f    = (const float*)d_in[5];
    const float* w_ih_r = (const float*)d_in[6];
    const float* w_hh_r = (const float*)d_in[7];
    const float* b_r    = (const float*)d_in[8];
    const float* w_ih_s = (const float*)d_in[9];
    const float* w_hh_s = (const float*)d_in[10];
    const float* b_s    = (const float*)d_in[11];
    const float* lin_w  = (const float*)d_in[12];
    const float* lin_b  = (const float*)d_in[13];
    const float* cstart = (const float*)d_in[14];
    const float* cend   = (const float*)d_in[15];
    const float* ctrans = (const float*)d_in[16];
    float* out = (float*)d_out;

    float *gbig, *hcat, *wpf, *wpr, *wps;
    cudaGetSymbolAddress((void**)&gbig, g_big);
    cudaGetSymbolAddress((void**)&hcat, g_hcat);
    cudaGetSymbolAddress((void**)&wpf, g_wpf);
    cudaGetSymbolAddress((void**)&wpr, g_wpr);
    cudaGetSymbolAddress((void**)&wps, g_wps);

    cudaFuncSetAttribute(word_scan_kernel,
                         cudaFuncAttributeMaxDynamicSharedMemorySize, 196608);
    cudaFuncSetAttribute(sent_scan_kernel,
                         cudaFuncAttributeMaxDynamicSharedMemorySize, 196608);

    pack_whh<<<(4 * HH * HH + 255) / 256, 256>>>(w_hh_f, wpf, HH);
    pack_whh<<<(4 * HH * HH + 255) / 256, 256>>>(w_hh_r, wpr, HH);
    pack_whh<<<(4 * H2 * H2 + 255) / 256, 256>>>(w_hh_s, wps, H2);

    dim3 g1(G4 / 128, (Bq * Tt) / 128);
    gemm_tf32<<<g1, 256, BUFS * 2 * 4>>>(x, w_ih_f, b_f, gbig, Bq * Tt, G4, Ff);
    gemm_tf32<<<g1, 256, BUFS * 2 * 4>>>(x, w_ih_r, b_r, gbig + GXR_OFF, Bq * Tt, G4, Ff);

    word_scan_kernel<<<128, 256, 196608>>>();

    dim3 g2(G8 / 128, (Bq * Tt) / 128);
    gemm_tf32<<<g2, 256, BUFS * 2 * 4>>>(hcat, w_ih_s, b_s, gbig, Bq * Tt, G8, H2);

    sent_scan_kernel<<<128, 256, 196608>>>();

    crf_kernel<<<1, 256>>>(y, lin_w, lin_b, cstart, cend, ctrans, out);
}

// round 13
// speedup vs baseline: 1.4421x; 1.2670x over previous
#include <cuda_runtime.h>
#include <math.h>

#define Bq 256
#define Tt 128
#define Ff 768
#define HH 256
#define G4 1024
#define H2 512
#define G8 2048
#define NC 16
#define GXR_OFF 33554432

typedef unsigned long long ull;

__device__ __forceinline__ void fma2(ull& d, ull a, ull b) {
    asm("fma.rn.f32x2 %0,%1,%2,%0;" : "+l"(d) : "l"(a), "l"(b));
}
__device__ __forceinline__ ull pk2(float lo, float hi) {
    ull r; asm("mov.b64 %0,{%1,%2};" : "=l"(r) : "f"(lo), "f"(hi)); return r;
}
__device__ __forceinline__ float2 up2(ull v) {
    float2 r; asm("mov.b64 {%0,%1},%2;" : "=f"(r.x), "=f"(r.y) : "l"(v)); return r;
}
__device__ __forceinline__ void mma_tf32(float c[4], const unsigned a[4], const unsigned b[2]) {
    asm("mma.sync.aligned.m16n8k8.row.col.f32.tf32.tf32.f32 "
        "{%0,%1,%2,%3}, {%4,%5,%6,%7}, {%8,%9}, {%0,%1,%2,%3};"
        : "+f"(c[0]), "+f"(c[1]), "+f"(c[2]), "+f"(c[3])
        : "r"(a[0]), "r"(a[1]), "r"(a[2]), "r"(a[3]), "r"(b[0]), "r"(b[1]));
}
__device__ __forceinline__ void cpa16(unsigned dst, const float* src) {
    asm volatile("cp.async.cg.shared.global [%0], [%1], 16;" :: "r"(dst), "l"(src));
}

__device__ float g_big[67108864];
__device__ float g_hcat[Bq * Tt * H2];
__device__ float g_wpf[HH * G4];
__device__ float g_wpr[HH * G4];
__device__ float g_wps[H2 * G8];
__device__ float g_wihs[G8 * H2];      // packed w_ih_s rows: n*4+g
__device__ float g_bs[G8];             // packed b_s
__device__ float g_hw[2][2][Bq][HH];
__device__ float g_hs[2][Bq][H2];

__device__ unsigned g_cnt[16 * 32];
__device__ unsigned g_gen[16 * 32];

__device__ __forceinline__ void group_barrier(int gid, unsigned n) {
    __syncthreads();
    if (threadIdx.x == 0) {
        volatile unsigned* genp = &g_gen[gid * 32];
        unsigned gen = *genp;
        __threadfence();
        if (atomicAdd(&g_cnt[gid * 32], 1u) == n - 1u) {
            atomicExch(&g_cnt[gid * 32], 0u);
            __threadfence();
            atomicExch(&g_gen[gid * 32], gen + 1u);
        } else {
            while (*genp == gen) { }
        }
        __threadfence();
    }
    __syncthreads();
}

__global__ void pack_whh(const float* __restrict__ in, float* __restrict__ out, int H) {
    int idx = blockIdx.x * blockDim.x + threadIdx.x;
    if (idx < 4 * H * H) {
        int g = idx & 3;
        int rem = idx >> 2;
        int n = rem % H;
        int k = rem / H;
        out[idx] = in[(size_t)(g * H + n) * H + k];
    }
}

// pack w_ih_s rows g*H2+n -> n*4+g (and bias)
__global__ void pack_wihs(const float* __restrict__ in, const float* __restrict__ bin,
                          float* __restrict__ out, float* __restrict__ bout) {
    int total = G8 * (H2 / 4);
    int idx = blockIdx.x * blockDim.x + threadIdx.x;
    if (idx < total) {
        int row = idx / (H2 / 4);
        int kc = (idx % (H2 / 4)) * 4;
        int n = row >> 2, g = row & 3;
        *(float4*)(out + (size_t)row * H2 + kc) =
            *(const float4*)(in + (size_t)(g * H2 + n) * H2 + kc);
    } else if (idx < total + G8) {
        int row = idx - total;
        int n = row >> 2, g = row & 3;
        bout[row] = bin[g * H2 + n];
    }
}

// ---------------- TF32 GEMM, cp.async double-buffered (kept) -------------------
#define GST 20
#define TSZ (128 * GST)
#define BUFS (2 * TSZ)
__global__ void __launch_bounds__(256) gemm_tf32(
    const float* __restrict__ A, const float* __restrict__ W,
    const float* __restrict__ bias, float* __restrict__ C,
    int M, int N, int K)
{
    extern __shared__ float gsm[];
    unsigned smb = (unsigned)__cvta_generic_to_shared(gsm);
    int tid = threadIdx.x;
    int lane = tid & 31, wid = tid >> 5;
    int wm = wid >> 2, wn = wid & 3;
    int lq = lane >> 2, lr4 = lane & 3;
    const float* Ab = A + (size_t)blockIdx.y * 128 * K;
    const float* Wb = W + (size_t)blockIdx.x * 128 * K;
    int ldr = tid >> 1;
    int ldk = (tid & 1) * 8;

    float acc[4][4][4];
#pragma unroll
    for (int i = 0; i < 4; i++)
#pragma unroll
        for (int j = 0; j < 4; j++)
#pragma unroll
            for (int r = 0; r < 4; r++) acc[i][j][r] = 0.f;

    {
        unsigned da = smb + (unsigned)(ldr * GST + ldk) * 4u;
        const float* sa = Ab + (size_t)ldr * K + ldk;
        cpa16(da, sa); cpa16(da + 16, sa + 4);
        unsigned db = smb + (unsigned)(TSZ + ldr * GST + ldk) * 4u;
        const float* sb = Wb + (size_t)ldr * K + ldk;
        cpa16(db, sb); cpa16(db + 16, sb + 4);
        asm volatile("cp.async.commit_group;");
    }
    int nk = K / 16;
    for (int kt = 0; kt < nk; kt++) {
        if (kt + 1 < nk) {
            int b = (kt + 1) & 1;
            int k0 = (kt + 1) * 16;
            unsigned da = smb + (unsigned)(b * BUFS + ldr * GST + ldk) * 4u;
            const float* sa = Ab + (size_t)ldr * K + k0 + ldk;
            cpa16(da, sa); cpa16(da + 16, sa + 4);
            unsigned db = smb + (unsigned)(b * BUFS + TSZ + ldr * GST + ldk) * 4u;
            const float* sb = Wb + (size_t)ldr * K + k0 + ldk;
            cpa16(db, sb); cpa16(db + 16, sb + 4);
            asm volatile("cp.async.commit_group;");
            asm volatile("cp.async.wait_group 1;");
        } else {
            asm volatile("cp.async.wait_group 0;");
        }
        __syncthreads();
        const unsigned* Abuf = (const unsigned*)gsm + (kt & 1) * BUFS;
        const unsigned* Bbuf = Abuf + TSZ;
#pragma unroll
        for (int ks = 0; ks < 2; ks++) {
            int kb = ks * 8;
            unsigned af[4][4];
#pragma unroll
            for (int mf = 0; mf < 4; mf++) {
                int row = wm * 64 + mf * 16 + lq;
                af[mf][0] = Abuf[row * GST + kb + lr4];
                af[mf][1] = Abuf[(row + 8) * GST + kb + lr4];
                af[mf][2] = Abuf[row * GST + kb + lr4 + 4];
                af[mf][3] = Abuf[(row + 8) * GST + kb + lr4 + 4];
            }
            unsigned bf[4][2];
#pragma unroll
            for (int nf = 0; nf < 4; nf++) {
                int n = wn * 32 + nf * 8 + lq;
                bf[nf][0] = Bbuf[n * GST + kb + lr4];
                bf[nf][1] = Bbuf[n * GST + kb + lr4 + 4];
            }
#pragma unroll
            for (int mf = 0; mf < 4; mf++)
#pragma unroll
                for (int nf = 0; nf < 4; nf++)
                    mma_tf32(acc[mf][nf], af[mf], bf[nf]);
        }
        __syncthreads();
    }
#pragma unroll
    for (int nf = 0; nf < 4; nf++) {
        int col0 = blockIdx.x * 128 + wn * 32 + nf * 8 + 2 * lr4;
        float b0v = bias[col0], b1v = bias[col0 + 1];
#pragma unroll
        for (int mf = 0; mf < 4; mf++) {
            int row0 = blockIdx.y * 128 + wm * 64 + mf * 16 + lq;
            float2 o0 = make_float2(acc[mf][nf][0] + b0v, acc[mf][nf][1] + b1v);
            float2 o1 = make_float2(acc[mf][nf][2] + b0v, acc[mf][nf][3] + b1v);
            *(float2*)(C + (size_t)row0 * N + col0) = o0;
            *(float2*)(C + (size_t)(row0 + 8) * N + col0) = o1;
        }
    }
}

__device__ __forceinline__ float sigf(float x) { return 1.f / (1.f + __expf(-x)); }

// ---------------- word BiLSTM scan (round-11, kept) -----------------------------
__global__ void __launch_bounds__(256) word_scan_kernel() {
    extern __shared__ __align__(16) float smp[];
    float* Ws = smp;                                  // [256][128]
    float2* Hd = (float2*)(smp + 256 * 128);          // [32][256] dup pairs
    int cta = blockIdx.x;
    int dir = cta & 1;
    int id = cta >> 1;
    int bt = id >> 3, nt = id & 7;
    int gid = dir * 8 + bt;
    const float* gxp = dir ? (g_big + GXR_OFF) : g_big;
    const float* wp  = dir ? g_wpr : g_wpf;
    int tid = threadIdx.x;
    int lane = tid & 31, wg = tid >> 5;
    int n = nt * 32 + lane;
    int b0 = bt * 32 + wg * 4;

    for (int i = tid; i < 256 * 32; i += 256) {
        int k = i >> 5, j4 = i & 31;
        ((float4*)Ws)[i] = ((const float4*)(wp + (size_t)k * G4 + nt * 128))[j4];
    }
    float* hb0 = &g_hw[dir][0][0][0];
    float* hb1 = &g_hw[dir][1][0][0];
    float c_reg[4] = {0.f, 0.f, 0.f, 0.f};
#pragma unroll
    for (int u = 0; u < 4; u++) hb0[(size_t)(b0 + u) * HH + n] = 0.f;
    group_barrier(gid, 8);

    for (int t = 0; t < Tt; t++) {
        int tt = dir ? (Tt - 1 - t) : t;
        const float* hp = (t & 1) ? hb1 : hb0;
        float* hn = (t & 1) ? hb0 : hb1;
        {
            const float4* hsrc = (const float4*)(hp + (size_t)(bt * 32) * HH);
            float4* hdst = (float4*)Hd;
            for (int idx = tid; idx < 32 * HH / 4; idx += 256) {
                float4 v = hsrc[idx];
                hdst[2 * idx]     = make_float4(v.x, v.x, v.y, v.y);
                hdst[2 * idx + 1] = make_float4(v.z, v.z, v.w, v.w);
            }
        }
        ull a01[4], a23[4];
#pragma unroll
        for (int u = 0; u < 4; u++) {
            const float* gp = gxp + ((size_t)(b0 + u) * Tt + tt) * G4 + n;
            a01[u] = pk2(gp[0], gp[HH]);
            a23[u] = pk2(gp[2 * HH], gp[3 * HH]);
        }
        __syncthreads();

        const ull* hrow = (const ull*)Hd + (size_t)(wg * 4) * HH;
        const float* wrow = Ws + lane * 4;
#pragma unroll 8
        for (int k = 0; k < HH; k++) {
            ulonglong2 wv = *(const ulonglong2*)(wrow + k * 128);
            ull h0 = hrow[k];
            ull h1 = hrow[HH + k];
            ull h2 = hrow[2 * HH + k];
            ull h3 = hrow[3 * HH + k];
            fma2(a01[0], h0, wv.x); fma2(a23[0], h0, wv.y);
            fma2(a01[1], h1, wv.x); fma2(a23[1], h1, wv.y);
            fma2(a01[2], h2, wv.x); fma2(a23[2], h2, wv.y);
            fma2(a01[3], h3, wv.x); fma2(a23[3], h3, wv.y);
        }
#pragma unroll
        for (int u = 0; u < 4; u++) {
            float2 p01 = up2(a01[u]);
            float2 p23 = up2(a23[u]);
            float ig = sigf(p01.x), fg = sigf(p01.y);
            float gg = tanhf(p23.x), og = sigf(p23.y);
            c_reg[u] = fg * c_reg[u] + ig * gg;
            float h = og * tanhf(c_reg[u]);
            hn[(size_t)(b0 + u) * HH + n] = h;
            g_hcat[((size_t)(b0 + u) * Tt + tt) * H2 + dir * HH + n] = h;
        }
        if (t < Tt - 1) group_barrier(gid, 8);
    }
}

// ---------------- sentence LSTM scan: TF32 MMA (gx now packed) ------------------
// 128 CTAs: bt(4) x nt(32). CTA = 64b x 64 packed gate cols (16 n), K=512.
__global__ void __launch_bounds__(256) sent_scan_kernel() {
    extern __shared__ __align__(16) float smp[];
    float2* Wf = (float2*)smp;                  // [kg64][nt8][lane32] = 128KB
    float*  Af = smp + 32768;                   // 4 arrays x 2048 floats = 32KB
    int cta = blockIdx.x;
    int bt = cta >> 5, nt_cta = cta & 31;
    int base = nt_cta * 64;
    int tid = threadIdx.x;
    int lane = tid & 31, wid = tid >> 5;
    int mt = wid >> 1, wn = wid & 1;
    int lq = lane >> 2, lr4 = lane & 3;
    int srow = tid >> 2;
    int scc  = tid & 3;

    // one-time: weights -> B-frag layout
    for (int s = tid; s < 64 * 8 * 32; s += 256) {
        int ls = s & 31, ntl = (s >> 5) & 7, kg = s >> 8;
        int gc = base + ntl * 8 + (ls >> 2);
        int k0 = kg * 8 + (ls & 3);
        Wf[s] = make_float2(g_wps[(size_t)k0 * G8 + gc],
                            g_wps[(size_t)(k0 + 4) * G8 + gc]);
    }
    float* hb0 = &g_hs[0][0][0];
    float* hb1 = &g_hs[1][0][0];
    for (int i = tid; i < 64 * 16; i += 256) {
        int r = i >> 4, nn = i & 15;
        hb0[(size_t)(bt * 64 + r) * H2 + nt_cta * 16 + nn] = 0.f;
    }
    float cst[4][2];
#pragma unroll
    for (int q = 0; q < 4; q++) { cst[q][0] = 0.f; cst[q][1] = 0.f; }
    group_barrier(8 + bt, 32);

    for (int t = 0; t < Tt; t++) {
        const float* hp = (t & 1) ? hb1 : hb0;
        float* hn = (t & 1) ? hb0 : hb1;
        float acc[4][4];
#pragma unroll
        for (int q = 0; q < 4; q++)
#pragma unroll
            for (int r = 0; r < 4; r++) acc[q][r] = 0.f;

#pragma unroll
        for (int c = 0; c < 4; c++) {
            {
                const float* hsr = hp + (size_t)(bt * 64 + srow) * H2 + c * 128;
                int mts = srow >> 4;
                int r8s = (srow >> 3) & 1;
                int lbs = (srow & 7) * 4;
                int khi = scc & 1;
                int arr = r8s + 2 * khi;
#pragma unroll
                for (int p = 0; p < 8; p++) {
                    float4 v = *(const float4*)(hsr + p * 16 + scc * 4);
                    int kgl = p * 2 + (scc >> 1);
                    *(float4*)(Af + arr * 2048 + ((kgl * 4 + mts) * 32 + lbs)) = v;
                }
            }
            __syncthreads();
#pragma unroll 4
            for (int kgl = 0; kgl < 16; kgl++) {
                int idx = (kgl * 4 + mt) * 32 + lane;
                unsigned af[4];
                af[0] = __float_as_uint(Af[idx]);
                af[1] = __float_as_uint(Af[2048 + idx]);
                af[2] = __float_as_uint(Af[4096 + idx]);
                af[3] = __float_as_uint(Af[6144 + idx]);
                int kg = c * 16 + kgl;
#pragma unroll
                for (int q = 0; q < 4; q++) {
                    float2 bv = Wf[((size_t)kg * 8 + wn * 4 + q) * 32 + lane];
                    unsigned bf[2] = {__float_as_uint(bv.x), __float_as_uint(bv.y)};
                    mma_tf32(acc[q], af, bf);
                }
            }
            __syncthreads();
        }

        // epilogue: gx (packed columns, contiguous float2) + gate pair exchange
        int row0 = bt * 64 + mt * 16 + lq;
#pragma unroll
        for (int q = 0; q < 4; q++) {
            int ntg = wn * 4 + q;
            int colb = base + ntg * 8 + 2 * lr4;
            float2 gx0 = *(const float2*)(g_big + ((size_t)row0 * Tt + t) * G8 + colb);
            float2 gx1 = *(const float2*)(g_big + ((size_t)(row0 + 8) * Tt + t) * G8 + colb);
            float v0 = acc[q][0] + gx0.x;
            float v1 = acc[q][1] + gx0.y;
            float v2 = acc[q][2] + gx1.x;
            float v3 = acc[q][3] + gx1.y;
            float p0 = __shfl_xor_sync(0xffffffffu, v0, 1);
            float p1 = __shfl_xor_sync(0xffffffffu, v1, 1);
            float p2 = __shfl_xor_sync(0xffffffffu, v2, 1);
            float p3 = __shfl_xor_sync(0xffffffffu, v3, 1);
            if (!(lr4 & 1)) {
                float c0 = cst[q][0], c1 = cst[q][1];
                c0 = sigf(v1) * c0 + sigf(v0) * tanhf(p0);
                c1 = sigf(v3) * c1 + sigf(v2) * tanhf(p2);
                cst[q][0] = c0; cst[q][1] = c1;
                float h0 = sigf(p1) * tanhf(c0);
                float h1 = sigf(p3) * tanhf(c1);
                int ng = nt_cta * 16 + ntg * 2 + (lr4 >> 1);
                hn[(size_t)row0 * H2 + ng] = h0;
                hn[(size_t)(row0 + 8) * H2 + ng] = h1;   // t=127 -> hb0 = hT
            }
        }
        if (t < Tt - 1) group_barrier(8 + bt, 32);
    }
}

// ---------------- emissions + CRF (single block) ------------------------------
__global__ void __launch_bounds__(256) crf_kernel(
    const int* __restrict__ y,
    const float* __restrict__ lin_w, const float* __restrict__ lin_b,
    const float* __restrict__ cstart, const float* __restrict__ cend,
    const float* __restrict__ ctrans, float* __restrict__ out)
{
    __shared__ float pool[NC * H2];
    __shared__ float e[Bq][NC];
    int tid = threadIdx.x;

    for (int idx = tid; idx < NC * H2 / 4; idx += 256)
        ((float4*)pool)[idx] = ((const float4*)lin_w)[idx];
    __syncthreads();
    {
        const float* hrow = &g_hs[0][tid][0];
        float acc[NC];
#pragma unroll
        for (int c = 0; c < NC; c++) acc[c] = lin_b[c];
        for (int k = 0; k < H2; k += 4) {
            float4 hv = *(const float4*)(hrow + k);
#pragma unroll
            for (int c = 0; c < NC; c++) {
                const float* wr = pool + c * H2 + k;
                acc[c] += hv.x * wr[0] + hv.y * wr[1] + hv.z * wr[2] + hv.w * wr[3];
            }
        }
#pragma unroll
        for (int c = 0; c < NC; c++) e[tid][c] = acc[c];
    }
    __syncthreads();
    if (tid < NC * NC) pool[tid] = ctrans[tid];
    __syncthreads();
    float* tr = pool;
    float* alpha = pool + 256;
    float* alpha2 = pool + 288;
    if (tid < NC) alpha[tid] = cstart[tid] + e[0][tid];
    __syncthreads();
    if (tid < 32) {
        for (int s = 1; s < Bq; s++) {
            if (tid < NC) {
                int j = tid;
                float m = -1e30f;
#pragma unroll
                for (int i = 0; i < NC; i++) m = fmaxf(m, alpha[i] + tr[i * NC + j]);
                float sum = 0.f;
#pragma unroll
                for (int i = 0; i < NC; i++) sum += expf(alpha[i] + tr[i * NC + j] - m);
                alpha2[j] = m + logf(sum) + e[s][j];
            }
            __syncwarp();
            if (tid < NC) alpha[tid] = alpha2[tid];
            __syncwarp();
        }
    }
    __syncthreads();
    if (tid == 0) {
        int yprev = y[0];
        float num = cstart[yprev] + e[0][yprev];
        for (int s = 1; s < Bq; s++) {
            int ys = y[s];
            num += tr[yprev * NC + ys] + e[s][ys];
            yprev = ys;
        }
        num += cend[yprev];
        float m = -1e30f;
        for (int i = 0; i < NC; i++) m = fmaxf(m, alpha[i] + cend[i]);
        float sum = 0.f;
        for (int i = 0; i < NC; i++) sum += expf(alpha[i] + cend[i] - m);
        out[0] = num - (m + logf(sum));
    }
}

// ---------------- launch ------------------------------------------------------
extern "C" void kernel_launch(void* const* d_in, const int* in_sizes, int n_in,
                              void* d_out, int out_size)
{
    const float* x      = (const float*)d_in[0];
    const int*   y      = (const int*)  d_in[1];
    const float* w_ih_f = (const float*)d_in[3];
    const float* w_hh_f = (const float*)d_in[4];
    const float* b_f    = (const float*)d_in[5];
    const float* w_ih_r = (const float*)d_in[6];
    const float* w_hh_r = (const float*)d_in[7];
    const float* b_r    = (const float*)d_in[8];
    const float* w_ih_s = (const float*)d_in[9];
    const float* w_hh_s = (const float*)d_in[10];
    const float* b_s    = (const float*)d_in[11];
    const float* lin_w  = (const float*)d_in[12];
    const float* lin_b  = (const float*)d_in[13];
    const float* cstart = (const float*)d_in[14];
    const float* cend   = (const float*)d_in[15];
    const float* ctrans = (const float*)d_in[16];
    float* out = (float*)d_out;

    float *gbig, *hcat, *wpf, *wpr, *wps, *wihs, *bs;
    cudaGetSymbolAddress((void**)&gbig, g_big);
    cudaGetSymbolAddress((void**)&hcat, g_hcat);
    cudaGetSymbolAddress((void**)&wpf, g_wpf);
    cudaGetSymbolAddress((void**)&wpr, g_wpr);
    cudaGetSymbolAddress((void**)&wps, g_wps);
    cudaGetSymbolAddress((void**)&wihs, g_wihs);
    cudaGetSymbolAddress((void**)&bs, g_bs);

    cudaFuncSetAttribute(word_scan_kernel,
                         cudaFuncAttributeMaxDynamicSharedMemorySize, 196608);
    cudaFuncSetAttribute(sent_scan_kernel,
                         cudaFuncAttributeMaxDynamicSharedMemorySize, 163840);

    pack_whh<<<(4 * HH * HH + 255) / 256, 256>>>(w_hh_f, wpf, HH);
    pack_whh<<<(4 * HH * HH + 255) / 256, 256>>>(w_hh_r, wpr, HH);
    pack_whh<<<(4 * H2 * H2 + 255) / 256, 256>>>(w_hh_s, wps, H2);
    pack_wihs<<<(G8 * (H2 / 4) + G8 + 255) / 256, 256>>>(w_ih_s, b_s, wihs, bs);

    dim3 g1(G4 / 128, (Bq * Tt) / 128);
    gemm_tf32<<<g1, 256, BUFS * 2 * 4>>>(x, w_ih_f, b_f, gbig, Bq * Tt, G4, Ff);
    gemm_tf32<<<g1, 256, BUFS * 2 * 4>>>(x, w_ih_r, b_r, gbig + GXR_OFF, Bq * Tt, G4, Ff);

    word_scan_kernel<<<128, 256, 196608>>>();

    dim3 g2(G8 / 128, (Bq * Tt) / 128);
    gemm_tf32<<<g2, 256, BUFS * 2 * 4>>>(hcat, wihs, bs, gbig, Bq * Tt, G8, H2);

    sent_scan_kernel<<<128, 256, 163840>>>();

    crf_kernel<<<1, 256>>>(y, lin_w, lin_b, cstart, cend, ctrans, out);
}

// round 14
// speedup vs baseline: 1.5686x; 1.0877x over previous
#include <cuda_runtime.h>
#include <math.h>

#define Bq 256
#define Tt 128
#define Ff 768
#define HH 256
#define G4 1024
#define H2 512
#define G8 2048
#define NC 16
#define GXR_OFF 33554432

typedef unsigned long long ull;

__device__ __forceinline__ void mma_tf32(float c[4], const unsigned a[4], const unsigned b[2]) {
    asm("mma.sync.aligned.m16n8k8.row.col.f32.tf32.tf32.f32 "
        "{%0,%1,%2,%3}, {%4,%5,%6,%7}, {%8,%9}, {%0,%1,%2,%3};"
        : "+f"(c[0]), "+f"(c[1]), "+f"(c[2]), "+f"(c[3])
        : "r"(a[0]), "r"(a[1]), "r"(a[2]), "r"(a[3]), "r"(b[0]), "r"(b[1]));
}
__device__ __forceinline__ void cpa16(unsigned dst, const float* src) {
    asm volatile("cp.async.cg.shared.global [%0], [%1], 16;" :: "r"(dst), "l"(src));
}

__device__ float g_big[67108864];
__device__ float g_hcat[Bq * Tt * H2];
__device__ float g_wpf[HH * G4];       // packed w_hh: [k][n*4+g]
__device__ float g_wpr[HH * G4];
__device__ float g_wps[H2 * G8];
__device__ float g_wihf[G4 * Ff];      // packed input weights (rows n*4+g)
__device__ float g_wihr[G4 * Ff];
__device__ float g_wihs[G8 * H2];
__device__ float g_bpf[G4];
__device__ float g_bpr[G4];
__device__ float g_bps[G8];
__device__ float g_hw[2][2][Bq][HH];
__device__ float g_hs[2][Bq][H2];

__device__ unsigned g_cnt[16 * 32];
__device__ unsigned g_gen[16 * 32];

__device__ __forceinline__ void group_barrier(int gid, unsigned n) {
    __syncthreads();
    if (threadIdx.x == 0) {
        volatile unsigned* genp = &g_gen[gid * 32];
        unsigned gen = *genp;
        __threadfence();
        if (atomicAdd(&g_cnt[gid * 32], 1u) == n - 1u) {
            atomicExch(&g_cnt[gid * 32], 0u);
            __threadfence();
            atomicExch(&g_gen[gid * 32], gen + 1u);
        } else {
            while (*genp == gen) { }
        }
        __threadfence();
    }
    __syncthreads();
}

__global__ void pack_whh(const float* __restrict__ in, float* __restrict__ out, int H) {
    int idx = blockIdx.x * blockDim.x + threadIdx.x;
    if (idx < 4 * H * H) {
        int g = idx & 3;
        int rem = idx >> 2;
        int n = rem % H;
        int k = rem / H;
        out[idx] = in[(size_t)(g * H + n) * H + k];
    }
}

// pack input weights rows g*H+n -> n*4+g (and bias); K multiple of 4
__global__ void pack_wih(const float* __restrict__ in, const float* __restrict__ bin,
                         float* __restrict__ out, float* __restrict__ bout,
                         int H, int K) {
    int N4 = 4 * H;
    int total = N4 * (K / 4);
    int idx = blockIdx.x * blockDim.x + threadIdx.x;
    if (idx < total) {
        int row = idx / (K / 4);
        int kc = (idx % (K / 4)) * 4;
        int n = row >> 2, g = row & 3;
        *(float4*)(out + (size_t)row * K + kc) =
            *(const float4*)(in + (size_t)(g * H + n) * K + kc);
    } else if (idx < total + N4) {
        int row = idx - total;
        int n = row >> 2, g = row & 3;
        bout[row] = bin[g * H + n];
    }
}

// ---------------- TF32 GEMM, cp.async double-buffered (kept) -------------------
#define GST 20
#define TSZ (128 * GST)
#define BUFS (2 * TSZ)
__global__ void __launch_bounds__(256) gemm_tf32(
    const float* __restrict__ A, const float* __restrict__ W,
    const float* __restrict__ bias, float* __restrict__ C,
    int M, int N, int K)
{
    extern __shared__ float gsm[];
    unsigned smb = (unsigned)__cvta_generic_to_shared(gsm);
    int tid = threadIdx.x;
    int lane = tid & 31, wid = tid >> 5;
    int wm = wid >> 2, wn = wid & 3;
    int lq = lane >> 2, lr4 = lane & 3;
    const float* Ab = A + (size_t)blockIdx.y * 128 * K;
    const float* Wb = W + (size_t)blockIdx.x * 128 * K;
    int ldr = tid >> 1;
    int ldk = (tid & 1) * 8;

    float acc[4][4][4];
#pragma unroll
    for (int i = 0; i < 4; i++)
#pragma unroll
        for (int j = 0; j < 4; j++)
#pragma unroll
            for (int r = 0; r < 4; r++) acc[i][j][r] = 0.f;

    {
        unsigned da = smb + (unsigned)(ldr * GST + ldk) * 4u;
        const float* sa = Ab + (size_t)ldr * K + ldk;
        cpa16(da, sa); cpa16(da + 16, sa + 4);
        unsigned db = smb + (unsigned)(TSZ + ldr * GST + ldk) * 4u;
        const float* sb = Wb + (size_t)ldr * K + ldk;
        cpa16(db, sb); cpa16(db + 16, sb + 4);
        asm volatile("cp.async.commit_group;");
    }
    int nk = K / 16;
    for (int kt = 0; kt < nk; kt++) {
        if (kt + 1 < nk) {
            int b = (kt + 1) & 1;
            int k0 = (kt + 1) * 16;
            unsigned da = smb + (unsigned)(b * BUFS + ldr * GST + ldk) * 4u;
            const float* sa = Ab + (size_t)ldr * K + k0 + ldk;
            cpa16(da, sa); cpa16(da + 16, sa + 4);
            unsigned db = smb + (unsigned)(b * BUFS + TSZ + ldr * GST + ldk) * 4u;
            const float* sb = Wb + (size_t)ldr * K + k0 + ldk;
            cpa16(db, sb); cpa16(db + 16, sb + 4);
            asm volatile("cp.async.commit_group;");
            asm volatile("cp.async.wait_group 1;");
        } else {
            asm volatile("cp.async.wait_group 0;");
        }
        __syncthreads();
        const unsigned* Abuf = (const unsigned*)gsm + (kt & 1) * BUFS;
        const unsigned* Bbuf = Abuf + TSZ;
#pragma unroll
        for (int ks = 0; ks < 2; ks++) {
            int kb = ks * 8;
            unsigned af[4][4];
#pragma unroll
            for (int mf = 0; mf < 4; mf++) {
                int row = wm * 64 + mf * 16 + lq;
                af[mf][0] = Abuf[row * GST + kb + lr4];
                af[mf][1] = Abuf[(row + 8) * GST + kb + lr4];
                af[mf][2] = Abuf[row * GST + kb + lr4 + 4];
                af[mf][3] = Abuf[(row + 8) * GST + kb + lr4 + 4];
            }
            unsigned bf[4][2];
#pragma unroll
            for (int nf = 0; nf < 4; nf++) {
                int n = wn * 32 + nf * 8 + lq;
                bf[nf][0] = Bbuf[n * GST + kb + lr4];
                bf[nf][1] = Bbuf[n * GST + kb + lr4 + 4];
            }
#pragma unroll
            for (int mf = 0; mf < 4; mf++)
#pragma unroll
                for (int nf = 0; nf < 4; nf++)
                    mma_tf32(acc[mf][nf], af[mf], bf[nf]);
        }
        __syncthreads();
    }
#pragma unroll
    for (int nf = 0; nf < 4; nf++) {
        int col0 = blockIdx.x * 128 + wn * 32 + nf * 8 + 2 * lr4;
        float b0v = bias[col0], b1v = bias[col0 + 1];
#pragma unroll
        for (int mf = 0; mf < 4; mf++) {
            int row0 = blockIdx.y * 128 + wm * 64 + mf * 16 + lq;
            float2 o0 = make_float2(acc[mf][nf][0] + b0v, acc[mf][nf][1] + b1v);
            float2 o1 = make_float2(acc[mf][nf][2] + b0v, acc[mf][nf][3] + b1v);
            *(float2*)(C + (size_t)row0 * N + col0) = o0;
            *(float2*)(C + (size_t)(row0 + 8) * N + col0) = o1;
        }
    }
}

__device__ __forceinline__ float sigf(float x) { return 1.f / (1.f + __expf(-x)); }

// ---------------- word BiLSTM scan: TF32 MMA -----------------------------------
// 128 CTAs: dir(2) x bt(4) x nt(16). CTA = 64b x 64 packed gate cols (16 n), K=256.
// Group = 16 CTAs per (dir,bt). smem: Wf 64KB + Af 32KB = 96KB.
__global__ void __launch_bounds__(256) word_scan_kernel() {
    extern __shared__ __align__(16) float smp[];
    float2* Wf = (float2*)smp;                  // [kg32][nt8][lane32] = 64KB
    float*  Af = smp + 16384;                   // 4 arrays x 2048 floats = 32KB
    int cta = blockIdx.x;
    int dir = cta & 1;
    int id = cta >> 1;
    int bt = id >> 4, nt_cta = id & 15;
    int gid = dir * 4 + bt;
    int base = nt_cta * 64;
    const float* gxp = dir ? (g_big + GXR_OFF) : g_big;
    const float* wp  = dir ? g_wpr : g_wpf;
    int tid = threadIdx.x;
    int lane = tid & 31, wid = tid >> 5;
    int mt = wid >> 1, wn = wid & 1;
    int lq = lane >> 2, lr4 = lane & 3;
    int srow = tid >> 2;
    int scc  = tid & 3;

    // one-time: weights -> B-frag layout (32 k-groups)
    for (int s = tid; s < 32 * 8 * 32; s += 256) {
        int ls = s & 31, ntl = (s >> 5) & 7, kg = s >> 8;
        int gc = base + ntl * 8 + (ls >> 2);
        int k0 = kg * 8 + (ls & 3);
        Wf[s] = make_float2(wp[(size_t)k0 * G4 + gc],
                            wp[(size_t)(k0 + 4) * G4 + gc]);
    }
    float* hb0 = &g_hw[dir][0][0][0];
    float* hb1 = &g_hw[dir][1][0][0];
    for (int i = tid; i < 64 * 16; i += 256) {
        int r = i >> 4, nn = i & 15;
        hb0[(size_t)(bt * 64 + r) * HH + nt_cta * 16 + nn] = 0.f;
    }
    float cst[4][2];
#pragma unroll
    for (int q = 0; q < 4; q++) { cst[q][0] = 0.f; cst[q][1] = 0.f; }
    group_barrier(gid, 16);

    for (int t = 0; t < Tt; t++) {
        int tt = dir ? (Tt - 1 - t) : t;
        const float* hp = (t & 1) ? hb1 : hb0;
        float* hn = (t & 1) ? hb0 : hb1;
        float acc[4][4];
#pragma unroll
        for (int q = 0; q < 4; q++)
#pragma unroll
            for (int r = 0; r < 4; r++) acc[q][r] = 0.f;

#pragma unroll
        for (int c = 0; c < 2; c++) {
            {
                const float* hsr = hp + (size_t)(bt * 64 + srow) * HH + c * 128;
                int mts = srow >> 4;
                int r8s = (srow >> 3) & 1;
                int lbs = (srow & 7) * 4;
                int khi = scc & 1;
                int arr = r8s + 2 * khi;
#pragma unroll
                for (int p = 0; p < 8; p++) {
                    float4 v = *(const float4*)(hsr + p * 16 + scc * 4);
                    int kgl = p * 2 + (scc >> 1);
                    *(float4*)(Af + arr * 2048 + ((kgl * 4 + mts) * 32 + lbs)) = v;
                }
            }
            __syncthreads();
#pragma unroll 4
            for (int kgl = 0; kgl < 16; kgl++) {
                int idx = (kgl * 4 + mt) * 32 + lane;
                unsigned af[4];
                af[0] = __float_as_uint(Af[idx]);
                af[1] = __float_as_uint(Af[2048 + idx]);
                af[2] = __float_as_uint(Af[4096 + idx]);
                af[3] = __float_as_uint(Af[6144 + idx]);
                int kg = c * 16 + kgl;
#pragma unroll
                for (int q = 0; q < 4; q++) {
                    float2 bv = Wf[((size_t)kg * 8 + wn * 4 + q) * 32 + lane];
                    unsigned bf[2] = {__float_as_uint(bv.x), __float_as_uint(bv.y)};
                    mma_tf32(acc[q], af, bf);
                }
            }
            __syncthreads();
        }

        // epilogue
        int row0 = bt * 64 + mt * 16 + lq;
#pragma unroll
        for (int q = 0; q < 4; q++) {
            int ntg = wn * 4 + q;
            int colb = base + ntg * 8 + 2 * lr4;
            float2 gx0 = *(const float2*)(gxp + ((size_t)row0 * Tt + tt) * G4 + colb);
            float2 gx1 = *(const float2*)(gxp + ((size_t)(row0 + 8) * Tt + tt) * G4 + colb);
            float v0 = acc[q][0] + gx0.x;
            float v1 = acc[q][1] + gx0.y;
            float v2 = acc[q][2] + gx1.x;
            float v3 = acc[q][3] + gx1.y;
            float p0 = __shfl_xor_sync(0xffffffffu, v0, 1);
            float p1 = __shfl_xor_sync(0xffffffffu, v1, 1);
            float p2 = __shfl_xor_sync(0xffffffffu, v2, 1);
            float p3 = __shfl_xor_sync(0xffffffffu, v3, 1);
            if (!(lr4 & 1)) {
                float c0 = cst[q][0], c1 = cst[q][1];
                c0 = sigf(v1) * c0 + sigf(v0) * tanhf(p0);
                c1 = sigf(v3) * c1 + sigf(v2) * tanhf(p2);
                cst[q][0] = c0; cst[q][1] = c1;
                float h0 = sigf(p1) * tanhf(c0);
                float h1 = sigf(p3) * tanhf(c1);
                int ng = nt_cta * 16 + ntg * 2 + (lr4 >> 1);
                hn[(size_t)row0 * HH + ng] = h0;
                hn[(size_t)(row0 + 8) * HH + ng] = h1;
                g_hcat[((size_t)row0 * Tt + tt) * H2 + dir * HH + ng] = h0;
                g_hcat[((size_t)(row0 + 8) * Tt + tt) * H2 + dir * HH + ng] = h1;
            }
        }
        if (t < Tt - 1) group_barrier(gid, 16);
    }
}

// ---------------- sentence LSTM scan: TF32 MMA (round-13, kept) -----------------
__global__ void __launch_bounds__(256) sent_scan_kernel() {
    extern __shared__ __align__(16) float smp[];
    float2* Wf = (float2*)smp;                  // [kg64][nt8][lane32] = 128KB
    float*  Af = smp + 32768;                   // 4 arrays x 2048 floats = 32KB
    int cta = blockIdx.x;
    int bt = cta >> 5, nt_cta = cta & 31;
    int base = nt_cta * 64;
    int tid = threadIdx.x;
    int lane = tid & 31, wid = tid >> 5;
    int mt = wid >> 1, wn = wid & 1;
    int lq = lane >> 2, lr4 = lane & 3;
    int srow = tid >> 2;
    int scc  = tid & 3;

    for (int s = tid; s < 64 * 8 * 32; s += 256) {
        int ls = s & 31, ntl = (s >> 5) & 7, kg = s >> 8;
        int gc = base + ntl * 8 + (ls >> 2);
        int k0 = kg * 8 + (ls & 3);
        Wf[s] = make_float2(g_wps[(size_t)k0 * G8 + gc],
                            g_wps[(size_t)(k0 + 4) * G8 + gc]);
    }
    float* hb0 = &g_hs[0][0][0];
    float* hb1 = &g_hs[1][0][0];
    for (int i = tid; i < 64 * 16; i += 256) {
        int r = i >> 4, nn = i & 15;
        hb0[(size_t)(bt * 64 + r) * H2 + nt_cta * 16 + nn] = 0.f;
    }
    float cst[4][2];
#pragma unroll
    for (int q = 0; q < 4; q++) { cst[q][0] = 0.f; cst[q][1] = 0.f; }
    group_barrier(8 + bt, 32);

    for (int t = 0; t < Tt; t++) {
        const float* hp = (t & 1) ? hb1 : hb0;
        float* hn = (t & 1) ? hb0 : hb1;
        float acc[4][4];
#pragma unroll
        for (int q = 0; q < 4; q++)
#pragma unroll
            for (int r = 0; r < 4; r++) acc[q][r] = 0.f;

#pragma unroll
        for (int c = 0; c < 4; c++) {
            {
                const float* hsr = hp + (size_t)(bt * 64 + srow) * H2 + c * 128;
                int mts = srow >> 4;
                int r8s = (srow >> 3) & 1;
                int lbs = (srow & 7) * 4;
                int khi = scc & 1;
                int arr = r8s + 2 * khi;
#pragma unroll
                for (int p = 0; p < 8; p++) {
                    float4 v = *(const float4*)(hsr + p * 16 + scc * 4);
                    int kgl = p * 2 + (scc >> 1);
                    *(float4*)(Af + arr * 2048 + ((kgl * 4 + mts) * 32 + lbs)) = v;
                }
            }
            __syncthreads();
#pragma unroll 4
            for (int kgl = 0; kgl < 16; kgl++) {
                int idx = (kgl * 4 + mt) * 32 + lane;
                unsigned af[4];
                af[0] = __float_as_uint(Af[idx]);
                af[1] = __float_as_uint(Af[2048 + idx]);
                af[2] = __float_as_uint(Af[4096 + idx]);
                af[3] = __float_as_uint(Af[6144 + idx]);
                int kg = c * 16 + kgl;
#pragma unroll
                for (int q = 0; q < 4; q++) {
                    float2 bv = Wf[((size_t)kg * 8 + wn * 4 + q) * 32 + lane];
                    unsigned bf[2] = {__float_as_uint(bv.x), __float_as_uint(bv.y)};
                    mma_tf32(acc[q], af, bf);
                }
            }
            __syncthreads();
        }

        int row0 = bt * 64 + mt * 16 + lq;
#pragma unroll
        for (int q = 0; q < 4; q++) {
            int ntg = wn * 4 + q;
            int colb = base + ntg * 8 + 2 * lr4;
            float2 gx0 = *(const float2*)(g_big + ((size_t)row0 * Tt + t) * G8 + colb);
            float2 gx1 = *(const float2*)(g_big + ((size_t)(row0 + 8) * Tt + t) * G8 + colb);
            float v0 = acc[q][0] + gx0.x;
            float v1 = acc[q][1] + gx0.y;
            float v2 = acc[q][2] + gx1.x;
            float v3 = acc[q][3] + gx1.y;
            float p0 = __shfl_xor_sync(0xffffffffu, v0, 1);
            float p1 = __shfl_xor_sync(0xffffffffu, v1, 1);
            float p2 = __shfl_xor_sync(0xffffffffu, v2, 1);
            float p3 = __shfl_xor_sync(0xffffffffu, v3, 1);
            if (!(lr4 & 1)) {
                float c0 = cst[q][0], c1 = cst[q][1];
                c0 = sigf(v1) * c0 + sigf(v0) * tanhf(p0);
                c1 = sigf(v3) * c1 + sigf(v2) * tanhf(p2);
                cst[q][0] = c0; cst[q][1] = c1;
                float h0 = sigf(p1) * tanhf(c0);
                float h1 = sigf(p3) * tanhf(c1);
                int ng = nt_cta * 16 + ntg * 2 + (lr4 >> 1);
                hn[(size_t)row0 * H2 + ng] = h0;
                hn[(size_t)(row0 + 8) * H2 + ng] = h1;   // t=127 -> hb0 = hT
            }
        }
        if (t < Tt - 1) group_barrier(8 + bt, 32);
    }
}

// ---------------- emissions + CRF (single block) ------------------------------
__global__ void __launch_bounds__(256) crf_kernel(
    const int* __restrict__ y,
    const float* __restrict__ lin_w, const float* __restrict__ lin_b,
    const float* __restrict__ cstart, const float* __restrict__ cend,
    const float* __restrict__ ctrans, float* __restrict__ out)
{
    __shared__ float pool[NC * H2];
    __shared__ float e[Bq][NC];
    int tid = threadIdx.x;

    for (int idx = tid; idx < NC * H2 / 4; idx += 256)
        ((float4*)pool)[idx] = ((const float4*)lin_w)[idx];
    __syncthreads();
    {
        const float* hrow = &g_hs[0][tid][0];
        float acc[NC];
#pragma unroll
        for (int c = 0; c < NC; c++) acc[c] = lin_b[c];
        for (int k = 0; k < H2; k += 4) {
            float4 hv = *(const float4*)(hrow + k);
#pragma unroll
            for (int c = 0; c < NC; c++) {
                const float* wr = pool + c * H2 + k;
                acc[c] += hv.x * wr[0] + hv.y * wr[1] + hv.z * wr[2] + hv.w * wr[3];
            }
        }
#pragma unroll
        for (int c = 0; c < NC; c++) e[tid][c] = acc[c];
    }
    __syncthreads();
    if (tid < NC * NC) pool[tid] = ctrans[tid];
    __syncthreads();
    float* tr = pool;
    float* alpha = pool + 256;
    float* alpha2 = pool + 288;
    if (tid < NC) alpha[tid] = cstart[tid] + e[0][tid];
    __syncthreads();
    if (tid < 32) {
        for (int s = 1; s < Bq; s++) {
            if (tid < NC) {
                int j = tid;
                float m = -1e30f;
#pragma unroll
                for (int i = 0; i < NC; i++) m = fmaxf(m, alpha[i] + tr[i * NC + j]);
                float sum = 0.f;
#pragma unroll
                for (int i = 0; i < NC; i++) sum += expf(alpha[i] + tr[i * NC + j] - m);
                alpha2[j] = m + logf(sum) + e[s][j];
            }
            __syncwarp();
            if (tid < NC) alpha[tid] = alpha2[tid];
            __syncwarp();
        }
    }
    __syncthreads();
    if (tid == 0) {
        int yprev = y[0];
        float num = cstart[yprev] + e[0][yprev];
        for (int s = 1; s < Bq; s++) {
            int ys = y[s];
            num += tr[yprev * NC + ys] + e[s][ys];
            yprev = ys;
        }
        num += cend[yprev];
        float m = -1e30f;
        for (int i = 0; i < NC; i++) m = fmaxf(m, alpha[i] + cend[i]);
        float sum = 0.f;
        for (int i = 0; i < NC; i++) sum += expf(alpha[i] + cend[i] - m);
        out[0] = num - (m + logf(sum));
    }
}

// ---------------- launch ------------------------------------------------------
extern "C" void kernel_launch(void* const* d_in, const int* in_sizes, int n_in,
                              void* d_out, int out_size)
{
    const float* x      = (const float*)d_in[0];
    const int*   y      = (const int*)  d_in[1];
    const float* w_ih_f = (const float*)d_in[3];
    const float* w_hh_f = (const float*)d_in[4];
    const float* b_f    = (const float*)d_in[5];
    const float* w_ih_r = (const float*)d_in[6];
    const float* w_hh_r = (const float*)d_in[7];
    const float* b_r    = (const float*)d_in[8];
    const float* w_ih_s = (const float*)d_in[9];
    const float* w_hh_s = (const float*)d_in[10];
    const float* b_s    = (const float*)d_in[11];
    const float* lin_w  = (const float*)d_in[12];
    const float* lin_b  = (const float*)d_in[13];
    const float* cstart = (const float*)d_in[14];
    const float* cend   = (const float*)d_in[15];
    const float* ctrans = (const float*)d_in[16];
    float* out = (float*)d_out;

    float *gbig, *hcat, *wpf, *wpr, *wps, *wihf, *wihr, *wihs, *bpf, *bpr, *bps;
    cudaGetSymbolAddress((void**)&gbig, g_big);
    cudaGetSymbolAddress((void**)&hcat, g_hcat);
    cudaGetSymbolAddress((void**)&wpf, g_wpf);
    cudaGetSymbolAddress((void**)&wpr, g_wpr);
    cudaGetSymbolAddress((void**)&wps, g_wps);
    cudaGetSymbolAddress((void**)&wihf, g_wihf);
    cudaGetSymbolAddress((void**)&wihr, g_wihr);
    cudaGetSymbolAddress((void**)&wihs, g_wihs);
    cudaGetSymbolAddress((void**)&bpf, g_bpf);
    cudaGetSymbolAddress((void**)&bpr, g_bpr);
    cudaGetSymbolAddress((void**)&bps, g_bps);

    cudaFuncSetAttribute(word_scan_kernel,
                         cudaFuncAttributeMaxDynamicSharedMemorySize, 98304);
    cudaFuncSetAttribute(sent_scan_kernel,
                         cudaFuncAttributeMaxDynamicSharedMemorySize, 163840);

    pack_whh<<<(4 * HH * HH + 255) / 256, 256>>>(w_hh_f, wpf, HH);
    pack_whh<<<(4 * HH * HH + 255) / 256, 256>>>(w_hh_r, wpr, HH);
    pack_whh<<<(4 * H2 * H2 + 255) / 256, 256>>>(w_hh_s, wps, H2);
    pack_wih<<<(G4 * (Ff / 4) + G4 + 255) / 256, 256>>>(w_ih_f, b_f, wihf, bpf, HH, Ff);
    pack_wih<<<(G4 * (Ff / 4) + G4 + 255) / 256, 256>>>(w_ih_r, b_r, wihr, bpr, HH, Ff);
    pack_wih<<<(G8 * (H2 / 4) + G8 + 255) / 256, 256>>>(w_ih_s, b_s, wihs, bps, H2, H2);

    dim3 g1(G4 / 128, (Bq * Tt) / 128);
    gemm_tf32<<<g1, 256, BUFS * 2 * 4>>>(x, wihf, bpf, gbig, Bq * Tt, G4, Ff);
    gemm_tf32<<<g1, 256, BUFS * 2 * 4>>>(x, wihr, bpr, gbig + GXR_OFF, Bq * Tt, G4, Ff);

    word_scan_kernel<<<128, 256, 98304>>>();

    dim3 g2(G8 / 128, (Bq * Tt) / 128);
    gemm_tf32<<<g2, 256, BUFS * 2 * 4>>>(hcat, wihs, bps, gbig, Bq * Tt, G8, H2);

    sent_scan_kernel<<<128, 256, 163840>>>();

    crf_kernel<<<1, 256>>>(y, lin_w, lin_b, cstart, cend, ctrans, out);
}

// round 15
// speedup vs baseline: 1.5696x; 1.0006x over previous
#include <cuda_runtime.h>
#include <math.h>

#define Bq 256
#define Tt 128
#define Ff 768
#define HH 256
#define G4 1024
#define H2 512
#define G8 2048
#define NC 16
#define GXR_OFF 33554432

__device__ __forceinline__ void mma_tf32(float c[4], const unsigned a[4], const unsigned b[2]) {
    asm("mma.sync.aligned.m16n8k8.row.col.f32.tf32.tf32.f32 "
        "{%0,%1,%2,%3}, {%4,%5,%6,%7}, {%8,%9}, {%0,%1,%2,%3};"
        : "+f"(c[0]), "+f"(c[1]), "+f"(c[2]), "+f"(c[3])
        : "r"(a[0]), "r"(a[1]), "r"(a[2]), "r"(a[3]), "r"(b[0]), "r"(b[1]));
}
__device__ __forceinline__ void cpa16(unsigned dst, const float* src) {
    asm volatile("cp.async.cg.shared.global [%0], [%1], 16;" :: "r"(dst), "l"(src));
}
__device__ __forceinline__ unsigned ldacq(const unsigned* p) {
    unsigned v; asm volatile("ld.acquire.gpu.global.b32 %0,[%1];" : "=r"(v) : "l"(p) : "memory"); return v;
}
__device__ __forceinline__ void strel(unsigned* p, unsigned v) {
    asm volatile("st.release.gpu.global.b32 [%0],%1;" :: "l"(p), "r"(v) : "memory");
}
__device__ __forceinline__ unsigned atomadd_rel(unsigned* p) {
    unsigned o; asm volatile("atom.release.gpu.global.add.u32 %0,[%1],1;" : "=r"(o) : "l"(p) : "memory"); return o;
}

__device__ float g_big[67108864];
__device__ float g_hcat[Bq * Tt * H2];
__device__ float g_wpf[HH * G4];       // packed w_hh: [k][n*4+g]
__device__ float g_wpr[HH * G4];
__device__ float g_wps[H2 * G8];
__device__ float g_wihf[G4 * Ff];      // packed input weights (rows n*4+g)
__device__ float g_wihr[G4 * Ff];
__device__ float g_wihs[G8 * H2];
__device__ float g_bpf[G4];
__device__ float g_bpr[G4];
__device__ float g_bps[G8];
__device__ float g_hw[2][2][Bq][HH];
__device__ float g_hs[2][Bq][H2];

__device__ unsigned g_cnt[16 * 32];
__device__ unsigned g_gen[16 * 32];

// group barrier: release arrive + acquire poll (no L1 flush; h reads use __ldcg)
__device__ __forceinline__ void group_barrier(int gid, unsigned n) {
    __syncthreads();
    if (threadIdx.x == 0) {
        unsigned* cnt = &g_cnt[gid * 32];
        unsigned* genp = &g_gen[gid * 32];
        unsigned gen = ldacq(genp);
        if (atomadd_rel(cnt) == n - 1u) {
            *(volatile unsigned*)cnt = 0u;
            strel(genp, gen + 1u);
        } else {
            while (ldacq(genp) == gen) { }
        }
    }
    __syncthreads();
}

__global__ void pack_whh(const float* __restrict__ in, float* __restrict__ out, int H) {
    int idx = blockIdx.x * blockDim.x + threadIdx.x;
    if (idx < 4 * H * H) {
        int g = idx & 3;
        int rem = idx >> 2;
        int n = rem % H;
        int k = rem / H;
        out[idx] = in[(size_t)(g * H + n) * H + k];
    }
}

__global__ void pack_wih(const float* __restrict__ in, const float* __restrict__ bin,
                         float* __restrict__ out, float* __restrict__ bout,
                         int H, int K) {
    int N4 = 4 * H;
    int total = N4 * (K / 4);
    int idx = blockIdx.x * blockDim.x + threadIdx.x;
    if (idx < total) {
        int row = idx / (K / 4);
        int kc = (idx % (K / 4)) * 4;
        int n = row >> 2, g = row & 3;
        *(float4*)(out + (size_t)row * K + kc) =
            *(const float4*)(in + (size_t)(g * H + n) * K + kc);
    } else if (idx < total + N4) {
        int row = idx - total;
        int n = row >> 2, g = row & 3;
        bout[row] = bin[g * H + n];
    }
}

// ---------------- TF32 GEMM, cp.async 3-stage pipelined ------------------------
#define GST 20
#define TSZ (128 * GST)
#define BUFS (2 * TSZ)          // floats per stage (A+B)
__global__ void __launch_bounds__(256) gemm_tf32(
    const float* __restrict__ A, const float* __restrict__ W,
    const float* __restrict__ bias, float* __restrict__ C,
    int M, int N, int K)
{
    extern __shared__ float gsm[];
    unsigned smb = (unsigned)__cvta_generic_to_shared(gsm);
    int tid = threadIdx.x;
    int lane = tid & 31, wid = tid >> 5;
    int wm = wid >> 2, wn = wid & 3;
    int lq = lane >> 2, lr4 = lane & 3;
    const float* Ab = A + (size_t)blockIdx.y * 128 * K;
    const float* Wb = W + (size_t)blockIdx.x * 128 * K;
    int ldr = tid >> 1;
    int ldk = (tid & 1) * 8;

    float acc[4][4][4];
#pragma unroll
    for (int i = 0; i < 4; i++)
#pragma unroll
        for (int j = 0; j < 4; j++)
#pragma unroll
            for (int r = 0; r < 4; r++) acc[i][j][r] = 0.f;

    int nk = K / 16;
    // prologue: tiles 0,1 -> stages 0,1
#pragma unroll
    for (int p = 0; p < 2; p++) {
        int k0 = p * 16;
        unsigned da = smb + (unsigned)(p * BUFS + ldr * GST + ldk) * 4u;
        const float* sa = Ab + (size_t)ldr * K + k0 + ldk;
        cpa16(da, sa); cpa16(da + 16, sa + 4);
        unsigned db = smb + (unsigned)(p * BUFS + TSZ + ldr * GST + ldk) * 4u;
        const float* sb = Wb + (size_t)ldr * K + k0 + ldk;
        cpa16(db, sb); cpa16(db + 16, sb + 4);
        asm volatile("cp.async.commit_group;");
    }
    int stage = 0, nstage = 2;
    for (int kt = 0; kt < nk; kt++) {
        __syncthreads();   // all warps finished reading the stage about to be overwritten
        if (kt + 2 < nk) {
            int k0 = (kt + 2) * 16;
            unsigned da = smb + (unsigned)(nstage * BUFS + ldr * GST + ldk) * 4u;
            const float* sa = Ab + (size_t)ldr * K + k0 + ldk;
            cpa16(da, sa); cpa16(da + 16, sa + 4);
            unsigned db = smb + (unsigned)(nstage * BUFS + TSZ + ldr * GST + ldk) * 4u;
            const float* sb = Wb + (size_t)ldr * K + k0 + ldk;
            cpa16(db, sb); cpa16(db + 16, sb + 4);
            asm volatile("cp.async.commit_group;");
            asm volatile("cp.async.wait_group 2;");
        } else if (kt + 1 < nk) {
            asm volatile("cp.async.wait_group 1;");
        } else {
            asm volatile("cp.async.wait_group 0;");
        }
        __syncthreads();
        const unsigned* Abuf = (const unsigned*)gsm + stage * BUFS;
        const unsigned* Bbuf = Abuf + TSZ;
#pragma unroll
        for (int ks = 0; ks < 2; ks++) {
            int kb = ks * 8;
            unsigned af[4][4];
#pragma unroll
            for (int mf = 0; mf < 4; mf++) {
                int row = wm * 64 + mf * 16 + lq;
                af[mf][0] = Abuf[row * GST + kb + lr4];
                af[mf][1] = Abuf[(row + 8) * GST + kb + lr4];
                af[mf][2] = Abuf[row * GST + kb + lr4 + 4];
                af[mf][3] = Abuf[(row + 8) * GST + kb + lr4 + 4];
            }
            unsigned bf[4][2];
#pragma unroll
            for (int nf = 0; nf < 4; nf++) {
                int n = wn * 32 + nf * 8 + lq;
                bf[nf][0] = Bbuf[n * GST + kb + lr4];
                bf[nf][1] = Bbuf[n * GST + kb + lr4 + 4];
            }
#pragma unroll
            for (int mf = 0; mf < 4; mf++)
#pragma unroll
                for (int nf = 0; nf < 4; nf++)
                    mma_tf32(acc[mf][nf], af[mf], bf[nf]);
        }
        stage = (stage == 2) ? 0 : stage + 1;
        nstage = (nstage == 2) ? 0 : nstage + 1;
    }
#pragma unroll
    for (int nf = 0; nf < 4; nf++) {
        int col0 = blockIdx.x * 128 + wn * 32 + nf * 8 + 2 * lr4;
        float b0v = bias[col0], b1v = bias[col0 + 1];
#pragma unroll
        for (int mf = 0; mf < 4; mf++) {
            int row0 = blockIdx.y * 128 + wm * 64 + mf * 16 + lq;
            float2 o0 = make_float2(acc[mf][nf][0] + b0v, acc[mf][nf][1] + b1v);
            float2 o1 = make_float2(acc[mf][nf][2] + b0v, acc[mf][nf][3] + b1v);
            *(float2*)(C + (size_t)row0 * N + col0) = o0;
            *(float2*)(C + (size_t)(row0 + 8) * N + col0) = o1;
        }
    }
}

__device__ __forceinline__ float sigf(float x) { return 1.f / (1.f + __expf(-x)); }

// ---------------- word BiLSTM scan: TF32 MMA (round-14; __ldcg staging) --------
__global__ void __launch_bounds__(256) word_scan_kernel() {
    extern __shared__ __align__(16) float smp[];
    float2* Wf = (float2*)smp;                  // [kg32][nt8][lane32] = 64KB
    float*  Af = smp + 16384;                   // 4 arrays x 2048 floats = 32KB
    int cta = blockIdx.x;
    int dir = cta & 1;
    int id = cta >> 1;
    int bt = id >> 4, nt_cta = id & 15;
    int gid = dir * 4 + bt;
    int base = nt_cta * 64;
    const float* gxp = dir ? (g_big + GXR_OFF) : g_big;
    const float* wp  = dir ? g_wpr : g_wpf;
    int tid = threadIdx.x;
    int lane = tid & 31, wid = tid >> 5;
    int mt = wid >> 1, wn = wid & 1;
    int lq = lane >> 2, lr4 = lane & 3;
    int srow = tid >> 2;
    int scc  = tid & 3;

    for (int s = tid; s < 32 * 8 * 32; s += 256) {
        int ls = s & 31, ntl = (s >> 5) & 7, kg = s >> 8;
        int gc = base + ntl * 8 + (ls >> 2);
        int k0 = kg * 8 + (ls & 3);
        Wf[s] = make_float2(wp[(size_t)k0 * G4 + gc],
                            wp[(size_t)(k0 + 4) * G4 + gc]);
    }
    float* hb0 = &g_hw[dir][0][0][0];
    float* hb1 = &g_hw[dir][1][0][0];
    for (int i = tid; i < 64 * 16; i += 256) {
        int r = i >> 4, nn = i & 15;
        hb0[(size_t)(bt * 64 + r) * HH + nt_cta * 16 + nn] = 0.f;
    }
    float cst[4][2];
#pragma unroll
    for (int q = 0; q < 4; q++) { cst[q][0] = 0.f; cst[q][1] = 0.f; }
    group_barrier(gid, 16);

    for (int t = 0; t < Tt; t++) {
        int tt = dir ? (Tt - 1 - t) : t;
        const float* hp = (t & 1) ? hb1 : hb0;
        float* hn = (t & 1) ? hb0 : hb1;
        float acc[4][4];
#pragma unroll
        for (int q = 0; q < 4; q++)
#pragma unroll
            for (int r = 0; r < 4; r++) acc[q][r] = 0.f;

#pragma unroll
        for (int c = 0; c < 2; c++) {
            {
                const float* hsr = hp + (size_t)(bt * 64 + srow) * HH + c * 128;
                int mts = srow >> 4;
                int r8s = (srow >> 3) & 1;
                int lbs = (srow & 7) * 4;
                int khi = scc & 1;
                int arr = r8s + 2 * khi;
#pragma unroll
                for (int p = 0; p < 8; p++) {
                    float4 v = __ldcg((const float4*)(hsr + p * 16 + scc * 4));
                    int kgl = p * 2 + (scc >> 1);
                    *(float4*)(Af + arr * 2048 + ((kgl * 4 + mts) * 32 + lbs)) = v;
                }
            }
            __syncthreads();
#pragma unroll 4
            for (int kgl = 0; kgl < 16; kgl++) {
                int idx = (kgl * 4 + mt) * 32 + lane;
                unsigned af[4];
                af[0] = __float_as_uint(Af[idx]);
                af[1] = __float_as_uint(Af[2048 + idx]);
                af[2] = __float_as_uint(Af[4096 + idx]);
                af[3] = __float_as_uint(Af[6144 + idx]);
                int kg = c * 16 + kgl;
#pragma unroll
                for (int q = 0; q < 4; q++) {
                    float2 bv = Wf[((size_t)kg * 8 + wn * 4 + q) * 32 + lane];
                    unsigned bf[2] = {__float_as_uint(bv.x), __float_as_uint(bv.y)};
                    mma_tf32(acc[q], af, bf);
                }
            }
            __syncthreads();
        }

        int row0 = bt * 64 + mt * 16 + lq;
#pragma unroll
        for (int q = 0; q < 4; q++) {
            int ntg = wn * 4 + q;
            int colb = base + ntg * 8 + 2 * lr4;
            float2 gx0 = *(const float2*)(gxp + ((size_t)row0 * Tt + tt) * G4 + colb);
            float2 gx1 = *(const float2*)(gxp + ((size_t)(row0 + 8) * Tt + tt) * G4 + colb);
            float v0 = acc[q][0] + gx0.x;
            float v1 = acc[q][1] + gx0.y;
            float v2 = acc[q][2] + gx1.x;
            float v3 = acc[q][3] + gx1.y;
            float p0 = __shfl_xor_sync(0xffffffffu, v0, 1);
            float p1 = __shfl_xor_sync(0xffffffffu, v1, 1);
            float p2 = __shfl_xor_sync(0xffffffffu, v2, 1);
            float p3 = __shfl_xor_sync(0xffffffffu, v3, 1);
            if (!(lr4 & 1)) {
                float c0 = cst[q][0], c1 = cst[q][1];
                c0 = sigf(v1) * c0 + sigf(v0) * tanhf(p0);
                c1 = sigf(v3) * c1 + sigf(v2) * tanhf(p2);
                cst[q][0] = c0; cst[q][1] = c1;
                float h0 = sigf(p1) * tanhf(c0);
                float h1 = sigf(p3) * tanhf(c1);
                int ng = nt_cta * 16 + ntg * 2 + (lr4 >> 1);
                hn[(size_t)row0 * HH + ng] = h0;
                hn[(size_t)(row0 + 8) * HH + ng] = h1;
                g_hcat[((size_t)row0 * Tt + tt) * H2 + dir * HH + ng] = h0;
                g_hcat[((size_t)(row0 + 8) * Tt + tt) * H2 + dir * HH + ng] = h1;
            }
        }
        if (t < Tt - 1) group_barrier(gid, 16);
    }
}

// ---------------- sentence LSTM scan: TF32 MMA (round-13; __ldcg staging) ------
__global__ void __launch_bounds__(256) sent_scan_kernel() {
    extern __shared__ __align__(16) float smp[];
    float2* Wf = (float2*)smp;                  // [kg64][nt8][lane32] = 128KB
    float*  Af = smp + 32768;                   // 4 arrays x 2048 floats = 32KB
    int cta = blockIdx.x;
    int bt = cta >> 5, nt_cta = cta & 31;
    int base = nt_cta * 64;
    int tid = threadIdx.x;
    int lane = tid & 31, wid = tid >> 5;
    int mt = wid >> 1, wn = wid & 1;
    int lq = lane >> 2, lr4 = lane & 3;
    int srow = tid >> 2;
    int scc  = tid & 3;

    for (int s = tid; s < 64 * 8 * 32; s += 256) {
        int ls = s & 31, ntl = (s >> 5) & 7, kg = s >> 8;
        int gc = base + ntl * 8 + (ls >> 2);
        int k0 = kg * 8 + (ls & 3);
        Wf[s] = make_float2(g_wps[(size_t)k0 * G8 + gc],
                            g_wps[(size_t)(k0 + 4) * G8 + gc]);
    }
    float* hb0 = &g_hs[0][0][0];
    float* hb1 = &g_hs[1][0][0];
    for (int i = tid; i < 64 * 16; i += 256) {
        int r = i >> 4, nn = i & 15;
        hb0[(size_t)(bt * 64 + r) * H2 + nt_cta * 16 + nn] = 0.f;
    }
    float cst[4][2];
#pragma unroll
    for (int q = 0; q < 4; q++) { cst[q][0] = 0.f; cst[q][1] = 0.f; }
    group_barrier(8 + bt, 32);

    for (int t = 0; t < Tt; t++) {
        const float* hp = (t & 1) ? hb1 : hb0;
        float* hn = (t & 1) ? hb0 : hb1;
        float acc[4][4];
#pragma unroll
        for (int q = 0; q < 4; q++)
#pragma unroll
            for (int r = 0; r < 4; r++) acc[q][r] = 0.f;

#pragma unroll
        for (int c = 0; c < 4; c++) {
            {
                const float* hsr = hp + (size_t)(bt * 64 + srow) * H2 + c * 128;
                int mts = srow >> 4;
                int r8s = (srow >> 3) & 1;
                int lbs = (srow & 7) * 4;
                int khi = scc & 1;
                int arr = r8s + 2 * khi;
#pragma unroll
                for (int p = 0; p < 8; p++) {
                    float4 v = __ldcg((const float4*)(hsr + p * 16 + scc * 4));
                    int kgl = p * 2 + (scc >> 1);
                    *(float4*)(Af + arr * 2048 + ((kgl * 4 + mts) * 32 + lbs)) = v;
                }
            }
            __syncthreads();
#pragma unroll 4
            for (int kgl = 0; kgl < 16; kgl++) {
                int idx = (kgl * 4 + mt) * 32 + lane;
                unsigned af[4];
                af[0] = __float_as_uint(Af[idx]);
                af[1] = __float_as_uint(Af[2048 + idx]);
                af[2] = __float_as_uint(Af[4096 + idx]);
                af[3] = __float_as_uint(Af[6144 + idx]);
                int kg = c * 16 + kgl;
#pragma unroll
                for (int q = 0; q < 4; q++) {
                    float2 bv = Wf[((size_t)kg * 8 + wn * 4 + q) * 32 + lane];
                    unsigned bf[2] = {__float_as_uint(bv.x), __float_as_uint(bv.y)};
                    mma_tf32(acc[q], af, bf);
                }
            }
            __syncthreads();
        }

        int row0 = bt * 64 + mt * 16 + lq;
#pragma unroll
        for (int q = 0; q < 4; q++) {
            int ntg = wn * 4 + q;
            int colb = base + ntg * 8 + 2 * lr4;
            float2 gx0 = *(const float2*)(g_big + ((size_t)row0 * Tt + t) * G8 + colb);
            float2 gx1 = *(const float2*)(g_big + ((size_t)(row0 + 8) * Tt + t) * G8 + colb);
            float v0 = acc[q][0] + gx0.x;
            float v1 = acc[q][1] + gx0.y;
            float v2 = acc[q][2] + gx1.x;
            float v3 = acc[q][3] + gx1.y;
            float p0 = __shfl_xor_sync(0xffffffffu, v0, 1);
            float p1 = __shfl_xor_sync(0xffffffffu, v1, 1);
            float p2 = __shfl_xor_sync(0xffffffffu, v2, 1);
            float p3 = __shfl_xor_sync(0xffffffffu, v3, 1);
            if (!(lr4 & 1)) {
                float c0 = cst[q][0], c1 = cst[q][1];
                c0 = sigf(v1) * c0 + sigf(v0) * tanhf(p0);
                c1 = sigf(v3) * c1 + sigf(v2) * tanhf(p2);
                cst[q][0] = c0; cst[q][1] = c1;
                float h0 = sigf(p1) * tanhf(c0);
                float h1 = sigf(p3) * tanhf(c1);
                int ng = nt_cta * 16 + ntg * 2 + (lr4 >> 1);
                hn[(size_t)row0 * H2 + ng] = h0;
                hn[(size_t)(row0 + 8) * H2 + ng] = h1;   // t=127 -> hb0 = hT
            }
        }
        if (t < Tt - 1) group_barrier(8 + bt, 32);
    }
}

// ---------------- emissions + CRF (single block) ------------------------------
__global__ void __launch_bounds__(256) crf_kernel(
    const int* __restrict__ y,
    const float* __restrict__ lin_w, const float* __restrict__ lin_b,
    const float* __restrict__ cstart, const float* __restrict__ cend,
    const float* __restrict__ ctrans, float* __restrict__ out)
{
    __shared__ float pool[NC * H2];
    __shared__ float e[Bq][NC];
    int tid = threadIdx.x;

    for (int idx = tid; idx < NC * H2 / 4; idx += 256)
        ((float4*)pool)[idx] = ((const float4*)lin_w)[idx];
    __syncthreads();
    {
        const float* hrow = &g_hs[0][tid][0];
        float acc[NC];
#pragma unroll
        for (int c = 0; c < NC; c++) acc[c] = lin_b[c];
        for (int k = 0; k < H2; k += 4) {
            float4 hv = *(const float4*)(hrow + k);
#pragma unroll
            for (int c = 0; c < NC; c++) {
                const float* wr = pool + c * H2 + k;
                acc[c] += hv.x * wr[0] + hv.y * wr[1] + hv.z * wr[2] + hv.w * wr[3];
            }
        }
#pragma unroll
        for (int c = 0; c < NC; c++) e[tid][c] = acc[c];
    }
    __syncthreads();
    if (tid < NC * NC) pool[tid] = ctrans[tid];
    __syncthreads();
    float* tr = pool;
    float* alpha = pool + 256;
    float* alpha2 = pool + 288;
    if (tid < NC) alpha[tid] = cstart[tid] + e[0][tid];
    __syncthreads();
    if (tid < 32) {
        for (int s = 1; s < Bq; s++) {
            if (tid < NC) {
                int j = tid;
                float m = -1e30f;
#pragma unroll
                for (int i = 0; i < NC; i++) m = fmaxf(m, alpha[i] + tr[i * NC + j]);
                float sum = 0.f;
#pragma unroll
                for (int i = 0; i < NC; i++) sum += expf(alpha[i] + tr[i * NC + j] - m);
                alpha2[j] = m + logf(sum) + e[s][j];
            }
            __syncwarp();
            if (tid < NC) alpha[tid] = alpha2[tid];
            __syncwarp();
        }
    }
    __syncthreads();
    if (tid == 0) {
        int yprev = y[0];
        float num = cstart[yprev] + e[0][yprev];
        for (int s = 1; s < Bq; s++) {
            int ys = y[s];
            num += tr[yprev * NC + ys] + e[s][ys];
            yprev = ys;
        }
        num += cend[yprev];
        float m = -1e30f;
        for (int i = 0; i < NC; i++) m = fmaxf(m, alpha[i] + cend[i]);
        float sum = 0.f;
        for (int i = 0; i < NC; i++) sum += expf(alpha[i] + cend[i] - m);
        out[0] = num - (m + logf(sum));
    }
}

// ---------------- launch ------------------------------------------------------
extern "C" void kernel_launch(void* const* d_in, const int* in_sizes, int n_in,
                              void* d_out, int out_size)
{
    const float* x      = (const float*)d_in[0];
    const int*   y      = (const int*)  d_in[1];
    const float* w_ih_f = (const float*)d_in[3];
    const float* w_hh_f = (const float*)d_in[4];
    const float* b_f    = (const float*)d_in[5];
    const float* w_ih_r = (const float*)d_in[6];
    const float* w_hh_r = (const float*)d_in[7];
    const float* b_r    = (const float*)d_in[8];
    const float* w_ih_s = (const float*)d_in[9];
    const float* w_hh_s = (const float*)d_in[10];
    const float* b_s    = (const float*)d_in[11];
    const float* lin_w  = (const float*)d_in[12];
    const float* lin_b  = (const float*)d_in[13];
    const float* cstart = (const float*)d_in[14];
    const float* cend   = (const float*)d_in[15];
    const float* ctrans = (const float*)d_in[16];
    float* out = (float*)d_out;

    float *gbig, *hcat, *wpf, *wpr, *wps, *wihf, *wihr, *wihs, *bpf, *bpr, *bps;
    cudaGetSymbolAddress((void**)&gbig, g_big);
    cudaGetSymbolAddress((void**)&hcat, g_hcat);
    cudaGetSymbolAddress((void**)&wpf, g_wpf);
    cudaGetSymbolAddress((void**)&wpr, g_wpr);
    cudaGetSymbolAddress((void**)&wps, g_wps);
    cudaGetSymbolAddress((void**)&wihf, g_wihf);
    cudaGetSymbolAddress((void**)&wihr, g_wihr);
    cudaGetSymbolAddress((void**)&wihs, g_wihs);
    cudaGetSymbolAddress((void**)&bpf, g_bpf);
    cudaGetSymbolAddress((void**)&bpr, g_bpr);
    cudaGetSymbolAddress((void**)&bps, g_bps);

    cudaFuncSetAttribute(gemm_tf32,
                         cudaFuncAttributeMaxDynamicSharedMemorySize, 3 * BUFS * 4);
    cudaFuncSetAttribute(word_scan_kernel,
                         cudaFuncAttributeMaxDynamicSharedMemorySize, 98304);
    cudaFuncSetAttribute(sent_scan_kernel,
                         cudaFuncAttributeMaxDynamicSharedMemorySize, 163840);

    pack_whh<<<(4 * HH * HH + 255) / 256, 256>>>(w_hh_f, wpf, HH);
    pack_whh<<<(4 * HH * HH + 255) / 256, 256>>>(w_hh_r, wpr, HH);
    pack_whh<<<(4 * H2 * H2 + 255) / 256, 256>>>(w_hh_s, wps, H2);
    pack_wih<<<(G4 * (Ff / 4) + G4 + 255) / 256, 256>>>(w_ih_f, b_f, wihf, bpf, HH, Ff);
    pack_wih<<<(G4 * (Ff / 4) + G4 + 255) / 256, 256>>>(w_ih_r, b_r, wihr, bpr, HH, Ff);
    pack_wih<<<(G8 * (H2 / 4) + G8 + 255) / 256, 256>>>(w_ih_s, b_s, wihs, bps, H2, H2);

    dim3 g1(G4 / 128, (Bq * Tt) / 128);
    gemm_tf32<<<g1, 256, 3 * BUFS * 4>>>(x, wihf, bpf, gbig, Bq * Tt, G4, Ff);
    gemm_tf32<<<g1, 256, 3 * BUFS * 4>>>(x, wihr, bpr, gbig + GXR_OFF, Bq * Tt, G4, Ff);

    word_scan_kernel<<<128, 256, 98304>>>();

    dim3 g2(G8 / 128, (Bq * Tt) / 128);
    gemm_tf32<<<g2, 256, 3 * BUFS * 4>>>(hcat, wihs, bps, gbig, Bq * Tt, G8, H2);

    sent_scan_kernel<<<128, 256, 163840>>>();

    crf_kernel<<<1, 256>>>(y, lin_w, lin_b, cstart, cend, ctrans, out);
}

// round 16
// speedup vs baseline: 1.8062x; 1.1507x over previous
#include <cuda_runtime.h>
#include <math.h>

#define Bq 256
#define Tt 128
#define Ff 768
#define HH 256
#define G4 1024
#define H2 512
#define G8 2048
#define NC 16
#define GXR_OFF 33554432

__device__ __forceinline__ void mma_tf32(float c[4], const unsigned a[4], const unsigned b[2]) {
    asm("mma.sync.aligned.m16n8k8.row.col.f32.tf32.tf32.f32 "
        "{%0,%1,%2,%3}, {%4,%5,%6,%7}, {%8,%9}, {%0,%1,%2,%3};"
        : "+f"(c[0]), "+f"(c[1]), "+f"(c[2]), "+f"(c[3])
        : "r"(a[0]), "r"(a[1]), "r"(a[2]), "r"(a[3]), "r"(b[0]), "r"(b[1]));
}
__device__ __forceinline__ void cpa16(unsigned dst, const float* src) {
    asm volatile("cp.async.cg.shared.global [%0], [%1], 16;" :: "r"(dst), "l"(src));
}
__device__ __forceinline__ unsigned ldacq(const unsigned* p) {
    unsigned v; asm volatile("ld.acquire.gpu.global.b32 %0,[%1];" : "=r"(v) : "l"(p) : "memory"); return v;
}
__device__ __forceinline__ void strel(unsigned* p, unsigned v) {
    asm volatile("st.release.gpu.global.b32 [%0],%1;" :: "l"(p), "r"(v) : "memory");
}
__device__ __forceinline__ unsigned atomadd_rel(unsigned* p) {
    unsigned o; asm volatile("atom.release.gpu.global.add.u32 %0,[%1],1;" : "=r"(o) : "l"(p) : "memory"); return o;
}

__device__ float g_big[67108864];
__device__ float g_hcat[Bq * Tt * H2];
__device__ float g_wpf[HH * G4];
__device__ float g_wpr[HH * G4];
__device__ float g_wps[H2 * G8];
__device__ float g_wihf[G4 * Ff];
__device__ float g_wihr[G4 * Ff];
__device__ float g_wihs[G8 * H2];
__device__ float g_bpf[G4];
__device__ float g_bpr[G4];
__device__ float g_bps[G8];
__device__ float g_hw[2][2][Bq][HH];
__device__ float g_hs[2][Bq][H2];

__device__ unsigned g_cnt[16 * 32];
__device__ unsigned g_gen[16 * 32];

__device__ __forceinline__ void group_barrier(int gid, unsigned n) {
    __syncthreads();
    if (threadIdx.x == 0) {
        unsigned* cnt = &g_cnt[gid * 32];
        unsigned* genp = &g_gen[gid * 32];
        unsigned gen = ldacq(genp);
        if (atomadd_rel(cnt) == n - 1u) {
            *(volatile unsigned*)cnt = 0u;
            strel(genp, gen + 1u);
        } else {
            while (ldacq(genp) == gen) { }
        }
    }
    __syncthreads();
}

// ---------------- single pack kernel (all 6 jobs) ------------------------------
__device__ __forceinline__ void do_whh(const float* in, float* out, int H, int idx) {
    if (idx < 4 * H * H) {
        int g = idx & 3;
        int rem = idx >> 2;
        int n = rem % H;
        int k = rem / H;
        out[idx] = in[(size_t)(g * H + n) * H + k];
    }
}
__device__ __forceinline__ void do_wih(const float* in, const float* bin,
                                       float* out, float* bout, int H, int K, int idx) {
    int N4 = 4 * H;
    int total = N4 * (K / 4);
    if (idx < total) {
        int row = idx / (K / 4);
        int kc = (idx % (K / 4)) * 4;
        int n = row >> 2, g = row & 3;
        *(float4*)(out + (size_t)row * K + kc) =
            *(const float4*)(in + (size_t)(g * H + n) * K + kc);
    } else if (idx < total + N4) {
        int row = idx - total;
        int n = row >> 2, g = row & 3;
        bout[row] = bin[g * H + n];
    }
}
__global__ void pack_all(const float* whf, const float* whr, const float* whs,
                         const float* wif, const float* bf,
                         const float* wir, const float* br,
                         const float* wis, const float* bs) {
    int idx = blockIdx.x * blockDim.x + threadIdx.x;
    switch (blockIdx.y) {
        case 0: do_whh(whf, g_wpf, HH, idx); break;
        case 1: do_whh(whr, g_wpr, HH, idx); break;
        case 2: do_whh(whs, g_wps, H2, idx); break;
        case 3: do_wih(wif, bf, g_wihf, g_bpf, HH, Ff, idx); break;
        case 4: do_wih(wir, br, g_wihr, g_bpr, HH, Ff, idx); break;
        case 5: do_wih(wis, bs, g_wihs, g_bps, H2, H2, idx); break;
    }
}

// ---------------- TF32 GEMM, cp.async 3-stage (kept) ---------------------------
#define GST 20
#define TSZ (128 * GST)
#define BUFS (2 * TSZ)
__global__ void __launch_bounds__(256) gemm_tf32(
    const float* __restrict__ A, const float* __restrict__ W,
    const float* __restrict__ bias, float* __restrict__ C,
    int M, int N, int K)
{
    extern __shared__ float gsm[];
    unsigned smb = (unsigned)__cvta_generic_to_shared(gsm);
    int tid = threadIdx.x;
    int lane = tid & 31, wid = tid >> 5;
    int wm = wid >> 2, wn = wid & 3;
    int lq = lane >> 2, lr4 = lane & 3;
    const float* Ab = A + (size_t)blockIdx.y * 128 * K;
    const float* Wb = W + (size_t)blockIdx.x * 128 * K;
    int ldr = tid >> 1;
    int ldk = (tid & 1) * 8;

    float acc[4][4][4];
#pragma unroll
    for (int i = 0; i < 4; i++)
#pragma unroll
        for (int j = 0; j < 4; j++)
#pragma unroll
            for (int r = 0; r < 4; r++) acc[i][j][r] = 0.f;

    int nk = K / 16;
#pragma unroll
    for (int p = 0; p < 2; p++) {
        int k0 = p * 16;
        unsigned da = smb + (unsigned)(p * BUFS + ldr * GST + ldk) * 4u;
        const float* sa = Ab + (size_t)ldr * K + k0 + ldk;
        cpa16(da, sa); cpa16(da + 16, sa + 4);
        unsigned db = smb + (unsigned)(p * BUFS + TSZ + ldr * GST + ldk) * 4u;
        const float* sb = Wb + (size_t)ldr * K + k0 + ldk;
        cpa16(db, sb); cpa16(db + 16, sb + 4);
        asm volatile("cp.async.commit_group;");
    }
    int stage = 0, nstage = 2;
    for (int kt = 0; kt < nk; kt++) {
        __syncthreads();
        if (kt + 2 < nk) {
            int k0 = (kt + 2) * 16;
            unsigned da = smb + (unsigned)(nstage * BUFS + ldr * GST + ldk) * 4u;
            const float* sa = Ab + (size_t)ldr * K + k0 + ldk;
            cpa16(da, sa); cpa16(da + 16, sa + 4);
            unsigned db = smb + (unsigned)(nstage * BUFS + TSZ + ldr * GST + ldk) * 4u;
            const float* sb = Wb + (size_t)ldr * K + k0 + ldk;
            cpa16(db, sb); cpa16(db + 16, sb + 4);
            asm volatile("cp.async.commit_group;");
            asm volatile("cp.async.wait_group 2;");
        } else if (kt + 1 < nk) {
            asm volatile("cp.async.wait_group 1;");
        } else {
            asm volatile("cp.async.wait_group 0;");
        }
        __syncthreads();
        const unsigned* Abuf = (const unsigned*)gsm + stage * BUFS;
        const unsigned* Bbuf = Abuf + TSZ;
#pragma unroll
        for (int ks = 0; ks < 2; ks++) {
            int kb = ks * 8;
            unsigned af[4][4];
#pragma unroll
            for (int mf = 0; mf < 4; mf++) {
                int row = wm * 64 + mf * 16 + lq;
                af[mf][0] = Abuf[row * GST + kb + lr4];
                af[mf][1] = Abuf[(row + 8) * GST + kb + lr4];
                af[mf][2] = Abuf[row * GST + kb + lr4 + 4];
                af[mf][3] = Abuf[(row + 8) * GST + kb + lr4 + 4];
            }
            unsigned bf[4][2];
#pragma unroll
            for (int nf = 0; nf < 4; nf++) {
                int n = wn * 32 + nf * 8 + lq;
                bf[nf][0] = Bbuf[n * GST + kb + lr4];
                bf[nf][1] = Bbuf[n * GST + kb + lr4 + 4];
            }
#pragma unroll
            for (int mf = 0; mf < 4; mf++)
#pragma unroll
                for (int nf = 0; nf < 4; nf++)
                    mma_tf32(acc[mf][nf], af[mf], bf[nf]);
        }
        stage = (stage == 2) ? 0 : stage + 1;
        nstage = (nstage == 2) ? 0 : nstage + 1;
    }
#pragma unroll
    for (int nf = 0; nf < 4; nf++) {
        int col0 = blockIdx.x * 128 + wn * 32 + nf * 8 + 2 * lr4;
        float b0v = bias[col0], b1v = bias[col0 + 1];
#pragma unroll
        for (int mf = 0; mf < 4; mf++) {
            int row0 = blockIdx.y * 128 + wm * 64 + mf * 16 + lq;
            float2 o0 = make_float2(acc[mf][nf][0] + b0v, acc[mf][nf][1] + b1v);
            float2 o1 = make_float2(acc[mf][nf][2] + b0v, acc[mf][nf][3] + b1v);
            *(float2*)(C + (size_t)row0 * N + col0) = o0;
            *(float2*)(C + (size_t)(row0 + 8) * N + col0) = o1;
        }
    }
}

__device__ __forceinline__ float sigf(float x) { return 1.f / (1.f + __expf(-x)); }

// ---------------- word BiLSTM scan: MMA, pipelined staging ---------------------
// 128 CTAs: dir(2) x bt(4) x nt(16). smem: Wf 64KB + Af 2x32KB = 128KB.
__global__ void __launch_bounds__(256) word_scan_kernel() {
    extern __shared__ __align__(16) float smp[];
    float2* Wf = (float2*)smp;                  // 64KB
    float*  Af = smp + 16384;                   // 2 bufs x 8192 floats
    int cta = blockIdx.x;
    int dir = cta & 1;
    int id = cta >> 1;
    int bt = id >> 4, nt_cta = id & 15;
    int gid = dir * 4 + bt;
    int base = nt_cta * 64;
    const float* gxp = dir ? (g_big + GXR_OFF) : g_big;
    const float* wp  = dir ? g_wpr : g_wpf;
    int tid = threadIdx.x;
    int lane = tid & 31, wid = tid >> 5;
    int mt = wid >> 1, wn = wid & 1;
    int lq = lane >> 2, lr4 = lane & 3;
    int srow = tid >> 2;
    int scc  = tid & 3;
    int mts = srow >> 4, r8s = (srow >> 3) & 1, lbs = (srow & 7) * 4;
    int arr = r8s + 2 * (scc & 1);

    for (int s = tid; s < 32 * 8 * 32; s += 256) {
        int ls = s & 31, ntl = (s >> 5) & 7, kg = s >> 8;
        int gc = base + ntl * 8 + (ls >> 2);
        int k0 = kg * 8 + (ls & 3);
        Wf[s] = make_float2(wp[(size_t)k0 * G4 + gc],
                            wp[(size_t)(k0 + 4) * G4 + gc]);
    }
    float* hb0 = &g_hw[dir][0][0][0];
    float* hb1 = &g_hw[dir][1][0][0];
    for (int i = tid; i < 64 * 16; i += 256) {
        int r = i >> 4, nn = i & 15;
        hb0[(size_t)(bt * 64 + r) * HH + nt_cta * 16 + nn] = 0.f;
    }
    float cst[4][2];
#pragma unroll
    for (int q = 0; q < 4; q++) { cst[q][0] = 0.f; cst[q][1] = 0.f; }
    group_barrier(gid, 16);

    for (int t = 0; t < Tt; t++) {
        int tt = dir ? (Tt - 1 - t) : t;
        const float* hp = (t & 1) ? hb1 : hb0;
        float* hn = (t & 1) ? hb0 : hb1;
        const float* hsr = hp + (size_t)(bt * 64 + srow) * HH;
        int row0 = bt * 64 + mt * 16 + lq;

        // hoist gx loads
        float2 gx0[4], gx1[4];
#pragma unroll
        for (int q = 0; q < 4; q++) {
            int colb = base + (wn * 4 + q) * 8 + 2 * lr4;
            gx0[q] = *(const float2*)(gxp + ((size_t)row0 * Tt + tt) * G4 + colb);
            gx1[q] = *(const float2*)(gxp + ((size_t)(row0 + 8) * Tt + tt) * G4 + colb);
        }
        float acc[4][4];
#pragma unroll
        for (int q = 0; q < 4; q++)
#pragma unroll
            for (int r = 0; r < 4; r++) acc[q][r] = 0.f;

        // stage chunk 0 -> buf 0
#pragma unroll
        for (int p = 0; p < 8; p++) {
            float4 v = __ldcg((const float4*)(hsr + p * 16 + scc * 4));
            int kgl = p * 2 + (scc >> 1);
            *(float4*)(Af + arr * 2048 + ((kgl * 4 + mts) * 32 + lbs)) = v;
        }
        __syncthreads();
#pragma unroll
        for (int c = 0; c < 2; c++) {
            float4 pre[8];
            if (c == 0) {
#pragma unroll
                for (int p = 0; p < 8; p++)
                    pre[p] = __ldcg((const float4*)(hsr + 128 + p * 16 + scc * 4));
            }
            const float* Ab = Af + (c & 1) * 8192;
#pragma unroll 4
            for (int kgl = 0; kgl < 16; kgl++) {
                int idx = (kgl * 4 + mt) * 32 + lane;
                unsigned af[4];
                af[0] = __float_as_uint(Ab[idx]);
                af[1] = __float_as_uint(Ab[2048 + idx]);
                af[2] = __float_as_uint(Ab[4096 + idx]);
                af[3] = __float_as_uint(Ab[6144 + idx]);
                int kg = c * 16 + kgl;
#pragma unroll
                for (int q = 0; q < 4; q++) {
                    float2 bv = Wf[((size_t)kg * 8 + wn * 4 + q) * 32 + lane];
                    unsigned bf[2] = {__float_as_uint(bv.x), __float_as_uint(bv.y)};
                    mma_tf32(acc[q], af, bf);
                }
            }
            if (c == 0) {
                float* Aw = Af + 8192;
#pragma unroll
                for (int p = 0; p < 8; p++) {
                    int kgl = p * 2 + (scc >> 1);
                    *(float4*)(Aw + arr * 2048 + ((kgl * 4 + mts) * 32 + lbs)) = pre[p];
                }
                __syncthreads();
            }
        }

#pragma unroll
        for (int q = 0; q < 4; q++) {
            int ntg = wn * 4 + q;
            float v0 = acc[q][0] + gx0[q].x;
            float v1 = acc[q][1] + gx0[q].y;
            float v2 = acc[q][2] + gx1[q].x;
            float v3 = acc[q][3] + gx1[q].y;
            float p0 = __shfl_xor_sync(0xffffffffu, v0, 1);
            float p1 = __shfl_xor_sync(0xffffffffu, v1, 1);
            float p2 = __shfl_xor_sync(0xffffffffu, v2, 1);
            float p3 = __shfl_xor_sync(0xffffffffu, v3, 1);
            if (!(lr4 & 1)) {
                float c0 = cst[q][0], c1 = cst[q][1];
                c0 = sigf(v1) * c0 + sigf(v0) * tanhf(p0);
                c1 = sigf(v3) * c1 + sigf(v2) * tanhf(p2);
                cst[q][0] = c0; cst[q][1] = c1;
                float h0 = sigf(p1) * tanhf(c0);
                float h1 = sigf(p3) * tanhf(c1);
                int ng = nt_cta * 16 + ntg * 2 + (lr4 >> 1);
                hn[(size_t)row0 * HH + ng] = h0;
                hn[(size_t)(row0 + 8) * HH + ng] = h1;
                g_hcat[((size_t)row0 * Tt + tt) * H2 + dir * HH + ng] = h0;
                g_hcat[((size_t)(row0 + 8) * Tt + tt) * H2 + dir * HH + ng] = h1;
            }
        }
        if (t < Tt - 1) group_barrier(gid, 16);
    }
}

// ---------------- sentence LSTM scan: MMA, pipelined staging -------------------
// 128 CTAs: bt(4) x nt(32). smem: Wf 128KB + Af 2x32KB = 192KB.
__global__ void __launch_bounds__(256) sent_scan_kernel() {
    extern __shared__ __align__(16) float smp[];
    float2* Wf = (float2*)smp;                  // 128KB
    float*  Af = smp + 32768;                   // 2 bufs x 8192 floats
    int cta = blockIdx.x;
    int bt = cta >> 5, nt_cta = cta & 31;
    int base = nt_cta * 64;
    int tid = threadIdx.x;
    int lane = tid & 31, wid = tid >> 5;
    int mt = wid >> 1, wn = wid & 1;
    int lq = lane >> 2, lr4 = lane & 3;
    int srow = tid >> 2;
    int scc  = tid & 3;
    int mts = srow >> 4, r8s = (srow >> 3) & 1, lbs = (srow & 7) * 4;
    int arr = r8s + 2 * (scc & 1);

    for (int s = tid; s < 64 * 8 * 32; s += 256) {
        int ls = s & 31, ntl = (s >> 5) & 7, kg = s >> 8;
        int gc = base + ntl * 8 + (ls >> 2);
        int k0 = kg * 8 + (ls & 3);
        Wf[s] = make_float2(g_wps[(size_t)k0 * G8 + gc],
                            g_wps[(size_t)(k0 + 4) * G8 + gc]);
    }
    float* hb0 = &g_hs[0][0][0];
    float* hb1 = &g_hs[1][0][0];
    for (int i = tid; i < 64 * 16; i += 256) {
        int r = i >> 4, nn = i & 15;
        hb0[(size_t)(bt * 64 + r) * H2 + nt_cta * 16 + nn] = 0.f;
    }
    float cst[4][2];
#pragma unroll
    for (int q = 0; q < 4; q++) { cst[q][0] = 0.f; cst[q][1] = 0.f; }
    group_barrier(8 + bt, 32);

    for (int t = 0; t < Tt; t++) {
        const float* hp = (t & 1) ? hb1 : hb0;
        float* hn = (t & 1) ? hb0 : hb1;
        const float* hsr = hp + (size_t)(bt * 64 + srow) * H2;
        int row0 = bt * 64 + mt * 16 + lq;

        float2 gx0[4], gx1[4];
#pragma unroll
        for (int q = 0; q < 4; q++) {
            int colb = base + (wn * 4 + q) * 8 + 2 * lr4;
            gx0[q] = *(const float2*)(g_big + ((size_t)row0 * Tt + t) * G8 + colb);
            gx1[q] = *(const float2*)(g_big + ((size_t)(row0 + 8) * Tt + t) * G8 + colb);
        }
        float acc[4][4];
#pragma unroll
        for (int q = 0; q < 4; q++)
#pragma unroll
            for (int r = 0; r < 4; r++) acc[q][r] = 0.f;

        // stage chunk 0 -> buf 0
#pragma unroll
        for (int p = 0; p < 8; p++) {
            float4 v = __ldcg((const float4*)(hsr + p * 16 + scc * 4));
            int kgl = p * 2 + (scc >> 1);
            *(float4*)(Af + arr * 2048 + ((kgl * 4 + mts) * 32 + lbs)) = v;
        }
        __syncthreads();
#pragma unroll
        for (int c = 0; c < 4; c++) {
            float4 pre[8];
            if (c < 3) {
#pragma unroll
                for (int p = 0; p < 8; p++)
                    pre[p] = __ldcg((const float4*)(hsr + (c + 1) * 128 + p * 16 + scc * 4));
            }
            const float* Ab = Af + (c & 1) * 8192;
#pragma unroll 4
            for (int kgl = 0; kgl < 16; kgl++) {
                int idx = (kgl * 4 + mt) * 32 + lane;
                unsigned af[4];
                af[0] = __float_as_uint(Ab[idx]);
                af[1] = __float_as_uint(Ab[2048 + idx]);
                af[2] = __float_as_uint(Ab[4096 + idx]);
                af[3] = __float_as_uint(Ab[6144 + idx]);
                int kg = c * 16 + kgl;
#pragma unroll
                for (int q = 0; q < 4; q++) {
                    float2 bv = Wf[((size_t)kg * 8 + wn * 4 + q) * 32 + lane];
                    unsigned bf[2] = {__float_as_uint(bv.x), __float_as_uint(bv.y)};
                    mma_tf32(acc[q], af, bf);
                }
            }
            if (c < 3) {
                float* Aw = Af + ((c + 1) & 1) * 8192;
#pragma unroll
                for (int p = 0; p < 8; p++) {
                    int kgl = p * 2 + (scc >> 1);
                    *(float4*)(Aw + arr * 2048 + ((kgl * 4 + mts) * 32 + lbs)) = pre[p];
                }
                __syncthreads();
            }
        }

#pragma unroll
        for (int q = 0; q < 4; q++) {
            int ntg = wn * 4 + q;
            float v0 = acc[q][0] + gx0[q].x;
            float v1 = acc[q][1] + gx0[q].y;
            float v2 = acc[q][2] + gx1[q].x;
            float v3 = acc[q][3] + gx1[q].y;
            float p0 = __shfl_xor_sync(0xffffffffu, v0, 1);
            float p1 = __shfl_xor_sync(0xffffffffu, v1, 1);
            float p2 = __shfl_xor_sync(0xffffffffu, v2, 1);
            float p3 = __shfl_xor_sync(0xffffffffu, v3, 1);
            if (!(lr4 & 1)) {
                float c0 = cst[q][0], c1 = cst[q][1];
                c0 = sigf(v1) * c0 + sigf(v0) * tanhf(p0);
                c1 = sigf(v3) * c1 + sigf(v2) * tanhf(p2);
                cst[q][0] = c0; cst[q][1] = c1;
                float h0 = sigf(p1) * tanhf(c0);
                float h1 = sigf(p3) * tanhf(c1);
                int ng = nt_cta * 16 + ntg * 2 + (lr4 >> 1);
                hn[(size_t)row0 * H2 + ng] = h0;
                hn[(size_t)(row0 + 8) * H2 + ng] = h1;   // t=127 -> hb0 = hT
            }
        }
        if (t < Tt - 1) group_barrier(8 + bt, 32);
    }
}

// ---------------- emissions + CRF (single block) ------------------------------
__global__ void __launch_bounds__(256) crf_kernel(
    const int* __restrict__ y,
    const float* __restrict__ lin_w, const float* __restrict__ lin_b,
    const float* __restrict__ cstart, const float* __restrict__ cend,
    const float* __restrict__ ctrans, float* __restrict__ out)
{
    __shared__ float pool[NC * H2];
    __shared__ float e[Bq][NC];
    int tid = threadIdx.x;

    for (int idx = tid; idx < NC * H2 / 4; idx += 256)
        ((float4*)pool)[idx] = ((const float4*)lin_w)[idx];
    __syncthreads();
    {
        const float* hrow = &g_hs[0][tid][0];
        float acc[NC];
#pragma unroll
        for (int c = 0; c < NC; c++) acc[c] = lin_b[c];
        for (int k = 0; k < H2; k += 4) {
            float4 hv = *(const float4*)(hrow + k);
#pragma unroll
            for (int c = 0; c < NC; c++) {
                const float* wr = pool + c * H2 + k;
                acc[c] += hv.x * wr[0] + hv.y * wr[1] + hv.z * wr[2] + hv.w * wr[3];
            }
        }
#pragma unroll
        for (int c = 0; c < NC; c++) e[tid][c] = acc[c];
    }
    __syncthreads();
    if (tid < NC * NC) pool[tid] = ctrans[tid];
    __syncthreads();
    float* tr = pool;
    float* alpha = pool + 256;
    float* alpha2 = pool + 288;
    if (tid < NC) alpha[tid] = cstart[tid] + e[0][tid];
    __syncthreads();
    if (tid < 32) {
        for (int s = 1; s < Bq; s++) {
            if (tid < NC) {
                int j = tid;
                float m = -1e30f;
#pragma unroll
                for (int i = 0; i < NC; i++) m = fmaxf(m, alpha[i] + tr[i * NC + j]);
                float sum = 0.f;
#pragma unroll
                for (int i = 0; i < NC; i++) sum += expf(alpha[i] + tr[i * NC + j] - m);
                alpha2[j] = m + logf(sum) + e[s][j];
            }
            __syncwarp();
            if (tid < NC) alpha[tid] = alpha2[tid];
            __syncwarp();
        }
    }
    __syncthreads();
    if (tid == 0) {
        int yprev = y[0];
        float num = cstart[yprev] + e[0][yprev];
        for (int s = 1; s < Bq; s++) {
            int ys = y[s];
            num += tr[yprev * NC + ys] + e[s][ys];
            yprev = ys;
        }
        num += cend[yprev];
        float m = -1e30f;
        for (int i = 0; i < NC; i++) m = fmaxf(m, alpha[i] + cend[i]);
        float sum = 0.f;
        for (int i = 0; i < NC; i++) sum += expf(alpha[i] + cend[i] - m);
        out[0] = num - (m + logf(sum));
    }
}

// ---------------- launch ------------------------------------------------------
extern "C" void kernel_launch(void* const* d_in, const int* in_sizes, int n_in,
                              void* d_out, int out_size)
{
    const float* x      = (const float*)d_in[0];
    const int*   y      = (const int*)  d_in[1];
    const float* w_ih_f = (const float*)d_in[3];
    const float* w_hh_f = (const float*)d_in[4];
    const float* b_f    = (const float*)d_in[5];
    const float* w_ih_r = (const float*)d_in[6];
    const float* w_hh_r = (const float*)d_in[7];
    const float* b_r    = (const float*)d_in[8];
    const float* w_ih_s = (const float*)d_in[9];
    const float* w_hh_s = (const float*)d_in[10];
    const float* b_s    = (const float*)d_in[11];
    const float* lin_w  = (const float*)d_in[12];
    const float* lin_b  = (const float*)d_in[13];
    const float* cstart = (const float*)d_in[14];
    const float* cend   = (const float*)d_in[15];
    const float* ctrans = (const float*)d_in[16];
    float* out = (float*)d_out;

    float *gbig, *hcat, *wihf, *wihr, *wihs, *bpf, *bpr, *bps;
    cudaGetSymbolAddress((void**)&gbig, g_big);
    cudaGetSymbolAddress((void**)&hcat, g_hcat);
    cudaGetSymbolAddress((void**)&wihf, g_wihf);
    cudaGetSymbolAddress((void**)&wihr, g_wihr);
    cudaGetSymbolAddress((void**)&wihs, g_wihs);
    cudaGetSymbolAddress((void**)&bpf, g_bpf);
    cudaGetSymbolAddress((void**)&bpr, g_bpr);
    cudaGetSymbolAddress((void**)&bps, g_bps);

    cudaFuncSetAttribute(gemm_tf32,
                         cudaFuncAttributeMaxDynamicSharedMemorySize, 3 * BUFS * 4);
    cudaFuncSetAttribute(word_scan_kernel,
                         cudaFuncAttributeMaxDynamicSharedMemorySize, 131072);
    cudaFuncSetAttribute(sent_scan_kernel,
                         cudaFuncAttributeMaxDynamicSharedMemorySize, 196608);

    // single pack launch (covers all 6 jobs)
    dim3 pg((4 * H2 * H2 + 255) / 256, 6);
    pack_all<<<pg, 256>>>(w_hh_f, w_hh_r, w_hh_s,
                          w_ih_f, b_f, w_ih_r, b_r, w_ih_s, b_s);

    dim3 g1(G4 / 128, (Bq * Tt) / 128);
    gemm_tf32<<<g1, 256, 3 * BUFS * 4>>>(x, wihf, bpf, gbig, Bq * Tt, G4, Ff);
    gemm_tf32<<<g1, 256, 3 * BUFS * 4>>>(x, wihr, bpr, gbig + GXR_OFF, Bq * Tt, G4, Ff);

    word_scan_kernel<<<128, 256, 131072>>>();

    dim3 g2(G8 / 128, (Bq * Tt) / 128);
    gemm_tf32<<<g2, 256, 3 * BUFS * 4>>>(hcat, wihs, bps, gbig, Bq * Tt, G8, H2);

    sent_scan_kernel<<<128, 256, 196608>>>();

    crf_kernel<<<1, 256>>>(y, lin_w, lin_b, cstart, cend, ctrans, out);
}

// round 17
// speedup vs baseline: 2.0352x; 1.1268x over previous
#include <cuda_runtime.h>
#include <cuda_bf16.h>
#include <math.h>

#define Bq 256
#define Tt 128
#define Ff 768
#define HH 256
#define G4 1024
#define H2 512
#define G8 2048
#define NC 16
#define GXR_OFF 33554432

__device__ __forceinline__ void mma_tf32(float c[4], const unsigned a[4], const unsigned b[2]) {
    asm("mma.sync.aligned.m16n8k8.row.col.f32.tf32.tf32.f32 "
        "{%0,%1,%2,%3}, {%4,%5,%6,%7}, {%8,%9}, {%0,%1,%2,%3};"
        : "+f"(c[0]), "+f"(c[1]), "+f"(c[2]), "+f"(c[3])
        : "r"(a[0]), "r"(a[1]), "r"(a[2]), "r"(a[3]), "r"(b[0]), "r"(b[1]));
}
__device__ __forceinline__ void mma_bf16(float c[4], const unsigned a[4], const unsigned b[2]) {
    asm("mma.sync.aligned.m16n8k16.row.col.f32.bf16.bf16.f32 "
        "{%0,%1,%2,%3}, {%4,%5,%6,%7}, {%8,%9}, {%0,%1,%2,%3};"
        : "+f"(c[0]), "+f"(c[1]), "+f"(c[2]), "+f"(c[3])
        : "r"(a[0]), "r"(a[1]), "r"(a[2]), "r"(a[3]), "r"(b[0]), "r"(b[1]));
}
__device__ __forceinline__ void cpa16(unsigned dst, const void* src) {
    asm volatile("cp.async.cg.shared.global [%0], [%1], 16;" :: "r"(dst), "l"(src));
}
__device__ __forceinline__ unsigned ldacq(const unsigned* p) {
    unsigned v; asm volatile("ld.acquire.gpu.global.b32 %0,[%1];" : "=r"(v) : "l"(p) : "memory"); return v;
}
__device__ __forceinline__ void strel(unsigned* p, unsigned v) {
    asm volatile("st.release.gpu.global.b32 [%0],%1;" :: "l"(p), "r"(v) : "memory");
}
__device__ __forceinline__ unsigned atomadd_rel(unsigned* p) {
    unsigned o; asm volatile("atom.release.gpu.global.add.u32 %0,[%1],1;" : "=r"(o) : "l"(p) : "memory"); return o;
}

__device__ float g_big[67108864];
__device__ __nv_bfloat16 g_xh[Bq * Tt * Ff];        // x in bf16
__device__ __nv_bfloat16 g_hcat_h[Bq * Tt * H2];    // word outputs in bf16
__device__ float g_wpf[HH * G4];
__device__ float g_wpr[HH * G4];
__device__ float g_wps[H2 * G8];
__device__ __nv_bfloat16 g_wihf_h[G4 * Ff];         // packed input weights, bf16
__device__ __nv_bfloat16 g_wihr_h[G4 * Ff];
__device__ __nv_bfloat16 g_wihs_h[G8 * H2];
__device__ float g_bpf[G4];
__device__ float g_bpr[G4];
__device__ float g_bps[G8];
__device__ float g_hw[2][2][Bq][HH];
__device__ float g_hs[2][Bq][H2];

__device__ unsigned g_cnt[16 * 32];
__device__ unsigned g_gen[16 * 32];

__device__ __forceinline__ void group_barrier(int gid, unsigned n) {
    __syncthreads();
    if (threadIdx.x == 0) {
        unsigned* cnt = &g_cnt[gid * 32];
        unsigned* genp = &g_gen[gid * 32];
        unsigned gen = ldacq(genp);
        if (atomadd_rel(cnt) == n - 1u) {
            *(volatile unsigned*)cnt = 0u;
            strel(genp, gen + 1u);
        } else {
            while (ldacq(genp) == gen) { }
        }
    }
    __syncthreads();
}

// ---------------- conversions / packing ----------------------------------------
__global__ void cvt_x(const float* __restrict__ in, __nv_bfloat16* __restrict__ out, int n) {
    int i = (blockIdx.x * blockDim.x + threadIdx.x) * 4;
    if (i < n) {
        float4 v = *(const float4*)(in + i);
        __nv_bfloat162 p0 = __floats2bfloat162_rn(v.x, v.y);
        __nv_bfloat162 p1 = __floats2bfloat162_rn(v.z, v.w);
        *(__nv_bfloat162*)(out + i) = p0;
        *(__nv_bfloat162*)(out + i + 2) = p1;
    }
}
__device__ __forceinline__ void do_whh(const float* in, float* out, int H, int idx) {
    if (idx < 4 * H * H) {
        int g = idx & 3;
        int rem = idx >> 2;
        int n = rem % H;
        int k = rem / H;
        out[idx] = in[(size_t)(g * H + n) * H + k];
    }
}
__device__ __forceinline__ void do_wih_h(const float* in, const float* bin,
                                         __nv_bfloat16* out, float* bout,
                                         int H, int K, int idx) {
    int N4 = 4 * H;
    int total = N4 * (K / 4);
    if (idx < total) {
        int row = idx / (K / 4);
        int kc = (idx % (K / 4)) * 4;
        int n = row >> 2, g = row & 3;
        float4 v = *(const float4*)(in + (size_t)(g * H + n) * K + kc);
        __nv_bfloat162 p0 = __floats2bfloat162_rn(v.x, v.y);
        __nv_bfloat162 p1 = __floats2bfloat162_rn(v.z, v.w);
        *(__nv_bfloat162*)(out + (size_t)row * K + kc) = p0;
        *(__nv_bfloat162*)(out + (size_t)row * K + kc + 2) = p1;
    } else if (idx < total + N4) {
        int row = idx - total;
        int n = row >> 2, g = row & 3;
        bout[row] = bin[g * H + n];
    }
}
__global__ void pack_all(const float* whf, const float* whr, const float* whs,
                         const float* wif, const float* bf,
                         const float* wir, const float* br,
                         const float* wis, const float* bs) {
    int idx = blockIdx.x * blockDim.x + threadIdx.x;
    switch (blockIdx.y) {
        case 0: do_whh(whf, g_wpf, HH, idx); break;
        case 1: do_whh(whr, g_wpr, HH, idx); break;
        case 2: do_whh(whs, g_wps, H2, idx); break;
        case 3: do_wih_h(wif, bf, g_wihf_h, g_bpf, HH, Ff, idx); break;
        case 4: do_wih_h(wir, br, g_wihr_h, g_bpr, HH, Ff, idx); break;
        case 5: do_wih_h(wis, bs, g_wihs_h, g_bps, H2, H2, idx); break;
    }
}

// ---------------- BF16 GEMM, cp.async 3-stage ----------------------------------
// smem rows: 24 bf16 (48B) stride -> conflict-free frag access.
#define HST 24
#define HTS (128 * HST)        // bf16 per matrix tile
#define HBUF (2 * HTS)         // bf16 per stage (A+B)
__global__ void __launch_bounds__(256) gemm_bf16(
    const __nv_bfloat16* __restrict__ A, const __nv_bfloat16* __restrict__ W,
    const float* __restrict__ bias, float* __restrict__ C,
    int M, int N, int K)
{
    extern __shared__ __nv_bfloat16 hsm[];
    unsigned smb = (unsigned)__cvta_generic_to_shared(hsm);
    int tid = threadIdx.x;
    int lane = tid & 31, wid = tid >> 5;
    int wm = wid >> 2, wn = wid & 3;
    int lq = lane >> 2, lr4 = lane & 3;
    const __nv_bfloat16* Ab = A + (size_t)blockIdx.y * 128 * K;
    const __nv_bfloat16* Wb = W + (size_t)blockIdx.x * 128 * K;
    int lrow = tid & 127;
    const __nv_bfloat16* src = (tid < 128) ? Ab : Wb;
    int dbase = (tid >> 7) * HTS + lrow * HST;

    float acc[4][4][4];
#pragma unroll
    for (int i = 0; i < 4; i++)
#pragma unroll
        for (int j = 0; j < 4; j++)
#pragma unroll
            for (int r = 0; r < 4; r++) acc[i][j][r] = 0.f;

    int nk = K / 16;
#pragma unroll
    for (int p = 0; p < 2; p++) {
        unsigned d = smb + (unsigned)(p * HBUF + dbase) * 2u;
        const __nv_bfloat16* s = src + (size_t)lrow * K + p * 16;
        cpa16(d, s); cpa16(d + 16, s + 8);
        asm volatile("cp.async.commit_group;");
    }
    int stage = 0, nstage = 2;
    for (int kt = 0; kt < nk; kt++) {
        __syncthreads();
        if (kt + 2 < nk) {
            unsigned d = smb + (unsigned)(nstage * HBUF + dbase) * 2u;
            const __nv_bfloat16* s = src + (size_t)lrow * K + (kt + 2) * 16;
            cpa16(d, s); cpa16(d + 16, s + 8);
            asm volatile("cp.async.commit_group;");
            asm volatile("cp.async.wait_group 2;");
        } else if (kt + 1 < nk) {
            asm volatile("cp.async.wait_group 1;");
        } else {
            asm volatile("cp.async.wait_group 0;");
        }
        __syncthreads();
        const unsigned* Abuf = (const unsigned*)hsm + stage * (HBUF / 2);
        const unsigned* Bbuf = Abuf + HTS / 2;
        unsigned af[4][4];
#pragma unroll
        for (int mf = 0; mf < 4; mf++) {
            int row = wm * 64 + mf * 16 + lq;
            af[mf][0] = Abuf[row * 12 + lr4];
            af[mf][1] = Abuf[(row + 8) * 12 + lr4];
            af[mf][2] = Abuf[row * 12 + 4 + lr4];
            af[mf][3] = Abuf[(row + 8) * 12 + 4 + lr4];
        }
        unsigned bfr[4][2];
#pragma unroll
        for (int nf = 0; nf < 4; nf++) {
            int n = wn * 32 + nf * 8 + lq;
            bfr[nf][0] = Bbuf[n * 12 + lr4];
            bfr[nf][1] = Bbuf[n * 12 + 4 + lr4];
        }
#pragma unroll
        for (int mf = 0; mf < 4; mf++)
#pragma unroll
            for (int nf = 0; nf < 4; nf++)
                mma_bf16(acc[mf][nf], af[mf], bfr[nf]);
        stage = (stage == 2) ? 0 : stage + 1;
        nstage = (nstage == 2) ? 0 : nstage + 1;
    }
#pragma unroll
    for (int nf = 0; nf < 4; nf++) {
        int col0 = blockIdx.x * 128 + wn * 32 + nf * 8 + 2 * lr4;
        float b0v = bias[col0], b1v = bias[col0 + 1];
#pragma unroll
        for (int mf = 0; mf < 4; mf++) {
            int row0 = blockIdx.y * 128 + wm * 64 + mf * 16 + lq;
            float2 o0 = make_float2(acc[mf][nf][0] + b0v, acc[mf][nf][1] + b1v);
            float2 o1 = make_float2(acc[mf][nf][2] + b0v, acc[mf][nf][3] + b1v);
            *(float2*)(C + (size_t)row0 * N + col0) = o0;
            *(float2*)(C + (size_t)(row0 + 8) * N + col0) = o1;
        }
    }
}

__device__ __forceinline__ float sigf(float x) { return 1.f / (1.f + __expf(-x)); }

// ---------------- word BiLSTM scan: MMA, pipelined staging (r16; bf16 hcat) ----
__global__ void __launch_bounds__(256) word_scan_kernel() {
    extern __shared__ __align__(16) float smp[];
    float2* Wf = (float2*)smp;                  // 64KB
    float*  Af = smp + 16384;                   // 2 bufs x 8192 floats
    int cta = blockIdx.x;
    int dir = cta & 1;
    int id = cta >> 1;
    int bt = id >> 4, nt_cta = id & 15;
    int gid = dir * 4 + bt;
    int base = nt_cta * 64;
    const float* gxp = dir ? (g_big + GXR_OFF) : g_big;
    const float* wp  = dir ? g_wpr : g_wpf;
    int tid = threadIdx.x;
    int lane = tid & 31, wid = tid >> 5;
    int mt = wid >> 1, wn = wid & 1;
    int lq = lane >> 2, lr4 = lane & 3;
    int srow = tid >> 2;
    int scc  = tid & 3;
    int mts = srow >> 4, r8s = (srow >> 3) & 1, lbs = (srow & 7) * 4;
    int arr = r8s + 2 * (scc & 1);

    for (int s = tid; s < 32 * 8 * 32; s += 256) {
        int ls = s & 31, ntl = (s >> 5) & 7, kg = s >> 8;
        int gc = base + ntl * 8 + (ls >> 2);
        int k0 = kg * 8 + (ls & 3);
        Wf[s] = make_float2(wp[(size_t)k0 * G4 + gc],
                            wp[(size_t)(k0 + 4) * G4 + gc]);
    }
    float* hb0 = &g_hw[dir][0][0][0];
    float* hb1 = &g_hw[dir][1][0][0];
    for (int i = tid; i < 64 * 16; i += 256) {
        int r = i >> 4, nn = i & 15;
        hb0[(size_t)(bt * 64 + r) * HH + nt_cta * 16 + nn] = 0.f;
    }
    float cst[4][2];
#pragma unroll
    for (int q = 0; q < 4; q++) { cst[q][0] = 0.f; cst[q][1] = 0.f; }
    group_barrier(gid, 16);

    for (int t = 0; t < Tt; t++) {
        int tt = dir ? (Tt - 1 - t) : t;
        const float* hp = (t & 1) ? hb1 : hb0;
        float* hn = (t & 1) ? hb0 : hb1;
        const float* hsr = hp + (size_t)(bt * 64 + srow) * HH;
        int row0 = bt * 64 + mt * 16 + lq;

        float2 gx0[4], gx1[4];
#pragma unroll
        for (int q = 0; q < 4; q++) {
            int colb = base + (wn * 4 + q) * 8 + 2 * lr4;
            gx0[q] = *(const float2*)(gxp + ((size_t)row0 * Tt + tt) * G4 + colb);
            gx1[q] = *(const float2*)(gxp + ((size_t)(row0 + 8) * Tt + tt) * G4 + colb);
        }
        float acc[4][4];
#pragma unroll
        for (int q = 0; q < 4; q++)
#pragma unroll
            for (int r = 0; r < 4; r++) acc[q][r] = 0.f;

#pragma unroll
        for (int p = 0; p < 8; p++) {
            float4 v = __ldcg((const float4*)(hsr + p * 16 + scc * 4));
            int kgl = p * 2 + (scc >> 1);
            *(float4*)(Af + arr * 2048 + ((kgl * 4 + mts) * 32 + lbs)) = v;
        }
        __syncthreads();
#pragma unroll
        for (int c = 0; c < 2; c++) {
            float4 pre[8];
            if (c == 0) {
#pragma unroll
                for (int p = 0; p < 8; p++)
                    pre[p] = __ldcg((const float4*)(hsr + 128 + p * 16 + scc * 4));
            }
            const float* Ab = Af + (c & 1) * 8192;
#pragma unroll 4
            for (int kgl = 0; kgl < 16; kgl++) {
                int idx = (kgl * 4 + mt) * 32 + lane;
                unsigned af[4];
                af[0] = __float_as_uint(Ab[idx]);
                af[1] = __float_as_uint(Ab[2048 + idx]);
                af[2] = __float_as_uint(Ab[4096 + idx]);
                af[3] = __float_as_uint(Ab[6144 + idx]);
                int kg = c * 16 + kgl;
#pragma unroll
                for (int q = 0; q < 4; q++) {
                    float2 bv = Wf[((size_t)kg * 8 + wn * 4 + q) * 32 + lane];
                    unsigned bfr[2] = {__float_as_uint(bv.x), __float_as_uint(bv.y)};
                    mma_tf32(acc[q], af, bfr);
                }
            }
            if (c == 0) {
                float* Aw = Af + 8192;
#pragma unroll
                for (int p = 0; p < 8; p++) {
                    int kgl = p * 2 + (scc >> 1);
                    *(float4*)(Aw + arr * 2048 + ((kgl * 4 + mts) * 32 + lbs)) = pre[p];
                }
                __syncthreads();
            }
        }

#pragma unroll
        for (int q = 0; q < 4; q++) {
            int ntg = wn * 4 + q;
            float v0 = acc[q][0] + gx0[q].x;
            float v1 = acc[q][1] + gx0[q].y;
            float v2 = acc[q][2] + gx1[q].x;
            float v3 = acc[q][3] + gx1[q].y;
            float p0 = __shfl_xor_sync(0xffffffffu, v0, 1);
            float p1 = __shfl_xor_sync(0xffffffffu, v1, 1);
            float p2 = __shfl_xor_sync(0xffffffffu, v2, 1);
            float p3 = __shfl_xor_sync(0xffffffffu, v3, 1);
            if (!(lr4 & 1)) {
                float c0 = cst[q][0], c1 = cst[q][1];
                c0 = sigf(v1) * c0 + sigf(v0) * tanhf(p0);
                c1 = sigf(v3) * c1 + sigf(v2) * tanhf(p2);
                cst[q][0] = c0; cst[q][1] = c1;
                float h0 = sigf(p1) * tanhf(c0);
                float h1 = sigf(p3) * tanhf(c1);
                int ng = nt_cta * 16 + ntg * 2 + (lr4 >> 1);
                hn[(size_t)row0 * HH + ng] = h0;
                hn[(size_t)(row0 + 8) * HH + ng] = h1;
                g_hcat_h[((size_t)row0 * Tt + tt) * H2 + dir * HH + ng] = __float2bfloat16(h0);
                g_hcat_h[((size_t)(row0 + 8) * Tt + tt) * H2 + dir * HH + ng] = __float2bfloat16(h1);
            }
        }
        if (t < Tt - 1) group_barrier(gid, 16);
    }
}

// ---------------- sentence LSTM scan: MMA, pipelined staging (r16) -------------
__global__ void __launch_bounds__(256) sent_scan_kernel() {
    extern __shared__ __align__(16) float smp[];
    float2* Wf = (float2*)smp;                  // 128KB
    float*  Af = smp + 32768;                   // 2 bufs x 8192 floats
    int cta = blockIdx.x;
    int bt = cta >> 5, nt_cta = cta & 31;
    int base = nt_cta * 64;
    int tid = threadIdx.x;
    int lane = tid & 31, wid = tid >> 5;
    int mt = wid >> 1, wn = wid & 1;
    int lq = lane >> 2, lr4 = lane & 3;
    int srow = tid >> 2;
    int scc  = tid & 3;
    int mts = srow >> 4, r8s = (srow >> 3) & 1, lbs = (srow & 7) * 4;
    int arr = r8s + 2 * (scc & 1);

    for (int s = tid; s < 64 * 8 * 32; s += 256) {
        int ls = s & 31, ntl = (s >> 5) & 7, kg = s >> 8;
        int gc = base + ntl * 8 + (ls >> 2);
        int k0 = kg * 8 + (ls & 3);
        Wf[s] = make_float2(g_wps[(size_t)k0 * G8 + gc],
                            g_wps[(size_t)(k0 + 4) * G8 + gc]);
    }
    float* hb0 = &g_hs[0][0][0];
    float* hb1 = &g_hs[1][0][0];
    for (int i = tid; i < 64 * 16; i += 256) {
        int r = i >> 4, nn = i & 15;
        hb0[(size_t)(bt * 64 + r) * H2 + nt_cta * 16 + nn] = 0.f;
    }
    float cst[4][2];
#pragma unroll
    for (int q = 0; q < 4; q++) { cst[q][0] = 0.f; cst[q][1] = 0.f; }
    group_barrier(8 + bt, 32);

    for (int t = 0; t < Tt; t++) {
        const float* hp = (t & 1) ? hb1 : hb0;
        float* hn = (t & 1) ? hb0 : hb1;
        const float* hsr = hp + (size_t)(bt * 64 + srow) * H2;
        int row0 = bt * 64 + mt * 16 + lq;

        float2 gx0[4], gx1[4];
#pragma unroll
        for (int q = 0; q < 4; q++) {
            int colb = base + (wn * 4 + q) * 8 + 2 * lr4;
            gx0[q] = *(const float2*)(g_big + ((size_t)row0 * Tt + t) * G8 + colb);
            gx1[q] = *(const float2*)(g_big + ((size_t)(row0 + 8) * Tt + t) * G8 + colb);
        }
        float acc[4][4];
#pragma unroll
        for (int q = 0; q < 4; q++)
#pragma unroll
            for (int r = 0; r < 4; r++) acc[q][r] = 0.f;

#pragma unroll
        for (int p = 0; p < 8; p++) {
            float4 v = __ldcg((const float4*)(hsr + p * 16 + scc * 4));
            int kgl = p * 2 + (scc >> 1);
            *(float4*)(Af + arr * 2048 + ((kgl * 4 + mts) * 32 + lbs)) = v;
        }
        __syncthreads();
#pragma unroll
        for (int c = 0; c < 4; c++) {
            float4 pre[8];
            if (c < 3) {
#pragma unroll
                for (int p = 0; p < 8; p++)
                    pre[p] = __ldcg((const float4*)(hsr + (c + 1) * 128 + p * 16 + scc * 4));
            }
            const float* Ab = Af + (c & 1) * 8192;
#pragma unroll 4
            for (int kgl = 0; kgl < 16; kgl++) {
                int idx = (kgl * 4 + mt) * 32 + lane;
                unsigned af[4];
                af[0] = __float_as_uint(Ab[idx]);
                af[1] = __float_as_uint(Ab[2048 + idx]);
                af[2] = __float_as_uint(Ab[4096 + idx]);
                af[3] = __float_as_uint(Ab[6144 + idx]);
                int kg = c * 16 + kgl;
#pragma unroll
                for (int q = 0; q < 4; q++) {
                    float2 bv = Wf[((size_t)kg * 8 + wn * 4 + q) * 32 + lane];
                    unsigned bfr[2] = {__float_as_uint(bv.x), __float_as_uint(bv.y)};
                    mma_tf32(acc[q], af, bfr);
                }
            }
            if (c < 3) {
                float* Aw = Af + ((c + 1) & 1) * 8192;
#pragma unroll
                for (int p = 0; p < 8; p++) {
                    int kgl = p * 2 + (scc >> 1);
                    *(float4*)(Aw + arr * 2048 + ((kgl * 4 + mts) * 32 + lbs)) = pre[p];
                }
                __syncthreads();
            }
        }

#pragma unroll
        for (int q = 0; q < 4; q++) {
            int ntg = wn * 4 + q;
            float v0 = acc[q][0] + gx0[q].x;
            float v1 = acc[q][1] + gx0[q].y;
            float v2 = acc[q][2] + gx1[q].x;
            float v3 = acc[q][3] + gx1[q].y;
            float p0 = __shfl_xor_sync(0xffffffffu, v0, 1);
            float p1 = __shfl_xor_sync(0xffffffffu, v1, 1);
            float p2 = __shfl_xor_sync(0xffffffffu, v2, 1);
            float p3 = __shfl_xor_sync(0xffffffffu, v3, 1);
            if (!(lr4 & 1)) {
                float c0 = cst[q][0], c1 = cst[q][1];
                c0 = sigf(v1) * c0 + sigf(v0) * tanhf(p0);
                c1 = sigf(v3) * c1 + sigf(v2) * tanhf(p2);
                cst[q][0] = c0; cst[q][1] = c1;
                float h0 = sigf(p1) * tanhf(c0);
                float h1 = sigf(p3) * tanhf(c1);
                int ng = nt_cta * 16 + ntg * 2 + (lr4 >> 1);
                hn[(size_t)row0 * H2 + ng] = h0;
                hn[(size_t)(row0 + 8) * H2 + ng] = h1;   // t=127 -> hb0 = hT
            }
        }
        if (t < Tt - 1) group_barrier(8 + bt, 32);
    }
}

// ---------------- emissions + CRF (single block) ------------------------------
__global__ void __launch_bounds__(256) crf_kernel(
    const int* __restrict__ y,
    const float* __restrict__ lin_w, const float* __restrict__ lin_b,
    const float* __restrict__ cstart, const float* __restrict__ cend,
    const float* __restrict__ ctrans, float* __restrict__ out)
{
    __shared__ float pool[NC * H2];
    __shared__ float e[Bq][NC];
    int tid = threadIdx.x;

    for (int idx = tid; idx < NC * H2 / 4; idx += 256)
        ((float4*)pool)[idx] = ((const float4*)lin_w)[idx];
    __syncthreads();
    {
        const float* hrow = &g_hs[0][tid][0];
        float acc[NC];
#pragma unroll
        for (int c = 0; c < NC; c++) acc[c] = lin_b[c];
        for (int k = 0; k < H2; k += 4) {
            float4 hv = *(const float4*)(hrow + k);
#pragma unroll
            for (int c = 0; c < NC; c++) {
                const float* wr = pool + c * H2 + k;
                acc[c] += hv.x * wr[0] + hv.y * wr[1] + hv.z * wr[2] + hv.w * wr[3];
            }
        }
#pragma unroll
        for (int c = 0; c < NC; c++) e[tid][c] = acc[c];
    }
    __syncthreads();
    if (tid < NC * NC) pool[tid] = ctrans[tid];
    __syncthreads();
    float* tr = pool;
    float* alpha = pool + 256;
    float* alpha2 = pool + 288;
    if (tid < NC) alpha[tid] = cstart[tid] + e[0][tid];
    __syncthreads();
    if (tid < 32) {
        for (int s = 1; s < Bq; s++) {
            if (tid < NC) {
                int j = tid;
                float m = -1e30f;
#pragma unroll
                for (int i = 0; i < NC; i++) m = fmaxf(m, alpha[i] + tr[i * NC + j]);
                float sum = 0.f;
#pragma unroll
                for (int i = 0; i < NC; i++) sum += expf(alpha[i] + tr[i * NC + j] - m);
                alpha2[j] = m + logf(sum) + e[s][j];
            }
            __syncwarp();
            if (tid < NC) alpha[tid] = alpha2[tid];
            __syncwarp();
        }
    }
    __syncthreads();
    if (tid == 0) {
        int yprev = y[0];
        float num = cstart[yprev] + e[0][yprev];
        for (int s = 1; s < Bq; s++) {
            int ys = y[s];
            num += tr[yprev * NC + ys] + e[s][ys];
            yprev = ys;
        }
        num += cend[yprev];
        float m = -1e30f;
        for (int i = 0; i < NC; i++) m = fmaxf(m, alpha[i] + cend[i]);
        float sum = 0.f;
        for (int i = 0; i < NC; i++) sum += expf(alpha[i] + cend[i] - m);
        out[0] = num - (m + logf(sum));
    }
}

// ---------------- launch ------------------------------------------------------
extern "C" void kernel_launch(void* const* d_in, const int* in_sizes, int n_in,
                              void* d_out, int out_size)
{
    const float* x      = (const float*)d_in[0];
    const int*   y      = (const int*)  d_in[1];
    const float* w_ih_f = (const float*)d_in[3];
    const float* w_hh_f = (const float*)d_in[4];
    const float* b_f    = (const float*)d_in[5];
    const float* w_ih_r = (const float*)d_in[6];
    const float* w_hh_r = (const float*)d_in[7];
    const float* b_r    = (const float*)d_in[8];
    const float* w_ih_s = (const float*)d_in[9];
    const float* w_hh_s = (const float*)d_in[10];
    const float* b_s    = (const float*)d_in[11];
    const float* lin_w  = (const float*)d_in[12];
    const float* lin_b  = (const float*)d_in[13];
    const float* cstart = (const float*)d_in[14];
    const float* cend   = (const float*)d_in[15];
    const float* ctrans = (const float*)d_in[16];
    float* out = (float*)d_out;

    float *gbig, *bpf, *bpr, *bps;
    __nv_bfloat16 *xh, *hcath, *wihfh, *wihrh, *wihsh;
    cudaGetSymbolAddress((void**)&gbig, g_big);
    cudaGetSymbolAddress((void**)&xh, g_xh);
    cudaGetSymbolAddress((void**)&hcath, g_hcat_h);
    cudaGetSymbolAddress((void**)&wihfh, g_wihf_h);
    cudaGetSymbolAddress((void**)&wihrh, g_wihr_h);
    cudaGetSymbolAddress((void**)&wihsh, g_wihs_h);
    cudaGetSymbolAddress((void**)&bpf, g_bpf);
    cudaGetSymbolAddress((void**)&bpr, g_bpr);
    cudaGetSymbolAddress((void**)&bps, g_bps);

    cudaFuncSetAttribute(gemm_bf16,
                         cudaFuncAttributeMaxDynamicSharedMemorySize, 3 * HBUF * 2);
    cudaFuncSetAttribute(word_scan_kernel,
                         cudaFuncAttributeMaxDynamicSharedMemorySize, 131072);
    cudaFuncSetAttribute(sent_scan_kernel,
                         cudaFuncAttributeMaxDynamicSharedMemorySize, 196608);

    dim3 pg((4 * H2 * H2 + 255) / 256, 6);
    pack_all<<<pg, 256>>>(w_hh_f, w_hh_r, w_hh_s,
                          w_ih_f, b_f, w_ih_r, b_r, w_ih_s, b_s);
    cvt_x<<<(Bq * Tt * Ff / 4 + 255) / 256, 256>>>(x, xh, Bq * Tt * Ff);

    dim3 g1(G4 / 128, (Bq * Tt) / 128);
    gemm_bf16<<<g1, 256, 3 * HBUF * 2>>>(xh, wihfh, bpf, gbig, Bq * Tt, G4, Ff);
    gemm_bf16<<<g1, 256, 3 * HBUF * 2>>>(xh, wihrh, bpr, gbig + GXR_OFF, Bq * Tt, G4, Ff);

    word_scan_kernel<<<128, 256, 131072>>>();

    dim3 g2(G8 / 128, (Bq * Tt) / 128);
    gemm_bf16<<<g2, 256, 3 * HBUF * 2>>>(hcath, wihsh, bps, gbig, Bq * Tt, G8, H2);

    sent_scan_kernel<<<128, 256, 196608>>>();

    crf_kernel<<<1, 256>>>(y, lin_w, lin_b, cstart, cend, ctrans, out);
}